// round 7
// baseline (speedup 1.0000x reference)
#include <cuda_runtime.h>
#include <cuda_fp16.h>
#include <cstdint>

#define NN   2000
#define HH   4
#define NDm  64
#define KK   20
#define TILE 8
#define BLT  128          // B*L
#define OUT_ELEMS (4*2000*32*64)

// GEMM dims (padded)
#define MP   2048
#define KP   2048
#define NTOT 8192
#define BK   64
#define AST  72           // padded smem stride (halves)
#define STAGE_BYTES 36864 // (128*72)*2 * 2 operands
#define NCHUNK (KP/BK)    // 32

// ---------------- scratch (device globals; no allocation) ----------------
__device__ __align__(256) __half g_Ah[(size_t)MP*KP];    // A[m=c][k=i]  (8.4 MB)
__device__ __align__(256) __half g_Bh[(size_t)NTOT*KP];  // B[n=bl*64+d][k=i] (33.5 MB)
__device__ int   g_tki[HH*NN*KK];
__device__ float g_tkv[HH*NN*KK];
__device__ float g_fa_fb[(size_t)NN*NN];                 // fallback final_adj

#define CPA16(dst, src) \
    asm volatile("cp.async.cg.shared.global [%0], [%1], 16;" :: "r"((uint32_t)(dst)), "l"(src) : "memory")

__device__ __forceinline__ uint32_t smem_u32(const void* p) {
    uint32_t a;
    asm("{ .reg .u64 t; cvta.to.shared.u64 t, %1; cvt.u32.u64 %0, t; }" : "=r"(a) : "l"(p));
    return a;
}

// ---------------- 0: zero A + final_adj ----------------
__global__ void zero_kernel(float* fa) {
    size_t idx = (size_t)blockIdx.x * blockDim.x + threadIdx.x;
    size_t stride = (size_t)gridDim.x * blockDim.x;
    uint4 z = make_uint4(0, 0, 0, 0);
    uint4* a4 = (uint4*)g_Ah;
    for (size_t p = idx; p < (size_t)MP * KP / 8; p += stride) a4[p] = z;
    for (size_t p = idx; p < (size_t)NN * NN; p += stride) fa[p] = 0.f;
}

// ---------------- 1: scores + softmax + top-20 ----------------
__global__ __launch_bounds__(256) void scores_topk_kernel(
    const float* __restrict__ e1, const float* __restrict__ e2,
    const float* __restrict__ temp)
{
    extern __shared__ float sm[];
    float* s   = sm;
    float* e1s = sm + TILE * NN;

    int h  = blockIdx.x / (NN / TILE);
    int n0 = (blockIdx.x % (NN / TILE)) * TILE;
    int tid = threadIdx.x;

    for (int i = tid; i < TILE * NDm; i += blockDim.x)
        e1s[i] = e1[((size_t)h * NN + n0 + i / NDm) * NDm + (i % NDm)];
    __syncthreads();

    for (int m = tid; m < NN; m += blockDim.x) {
        float acc[TILE];
#pragma unroll
        for (int r = 0; r < TILE; r++) acc[r] = 0.f;
        const float* e2p = e2 + (size_t)h * NDm * NN + m;
#pragma unroll 8
        for (int d = 0; d < NDm; d++) {
            float b = e2p[(size_t)d * NN];
#pragma unroll
            for (int r = 0; r < TILE; r++) acc[r] = fmaf(e1s[r * NDm + d], b, acc[r]);
        }
#pragma unroll
        for (int r = 0; r < TILE; r++) s[r * NN + m] = acc[r];
    }
    __syncthreads();

    int w = tid >> 5, lane = tid & 31;
    float invT = 1.0f / temp[h];
    float* sw = s + w * NN;

    float M = 0.f;
    for (int m = lane; m < NN; m += 32) {
        float a = fmaxf(sw[m], 0.f) * invT;
        sw[m] = a;
        M = fmaxf(M, a);
    }
#pragma unroll
    for (int o = 16; o; o >>= 1) M = fmaxf(M, __shfl_xor_sync(0xffffffffu, M, o));

    float S = 0.f;
    for (int m = lane; m < NN; m += 32) S += __expf(sw[m] - M);
#pragma unroll
    for (int o = 16; o; o >>= 1) S += __shfl_xor_sync(0xffffffffu, S, o);

    int base = (h * NN + n0 + w) * KK;
    float ssel = 0.f;
    for (int k = 0; k < KK; k++) {
        float best = -1.f; int bi = NN;
        for (int m = lane; m < NN; m += 32) {
            float v = sw[m];
            if (v > best) { best = v; bi = m; }
        }
#pragma unroll
        for (int o = 16; o; o >>= 1) {
            float ov = __shfl_xor_sync(0xffffffffu, best, o);
            int   oi = __shfl_xor_sync(0xffffffffu, bi,   o);
            if (ov > best || (ov == best && oi < bi)) { best = ov; bi = oi; }
        }
        float e = __expf(best - M);
        ssel += e;
        if (lane == 0) { g_tki[base + k] = bi; g_tkv[base + k] = e; }
        sw[bi] = -1.f;
        __syncwarp();
    }
    float denom = ssel + 1e-8f * S;
    __syncwarp();
    if (lane < KK) g_tkv[base + lane] = g_tkv[base + lane] / denom;
}

// ---------------- 2: per-row union + edge MLP -> A (fp16, [c][i]) + dense fa ----------------
__global__ __launch_bounds__(256) void build_rows_kernel(
    const float* __restrict__ ew1, const float* __restrict__ eb1,
    const float* __restrict__ ew2, const float* __restrict__ eb2,
    float* __restrict__ fa)
{
    __shared__ float s_ew1[HH * 8];
    __shared__ float s_eb1[8];
    __shared__ float s_ew2[8];
    __shared__ int   s_js[8][80];
    __shared__ float s_vs[8][80];

    int tid = threadIdx.x;
    if (tid < 32) s_ew1[tid] = ew1[tid];
    else if (tid < 40) s_eb1[tid - 32] = eb1[tid - 32];
    else if (tid < 48) s_ew2[tid - 40] = ew2[tid - 40];
    float beta2 = eb2[0];
    __syncthreads();

    int w = tid >> 5, lane = tid & 31;
    int i = blockIdx.x * 8 + w;

    for (int e = lane; e < 80; e += 32) {
        int hh = e / KK, k = e % KK;
        s_js[w][e] = g_tki[(hh * NN + i) * KK + k];
        s_vs[w][e] = g_tkv[(hh * NN + i) * KK + k];
    }
    __syncwarp();

    for (int p = 0; p < 3; p++) {
        int e = lane + p * 32;
        bool owned = false;
        int j = -1;
        if (e < 80) {
            j = s_js[w][e];
            owned = true;
            for (int q = 0; q < e; q++)
                if (s_js[w][q] == j) { owned = false; break; }
        }
        if (owned) {
            float v[HH];
            float vsum = 0.f;
#pragma unroll
            for (int hh = 0; hh < HH; hh++) {
                float vv = 0.f;
                for (int k = 0; k < KK; k++)
                    if (s_js[w][hh * KK + k] == j) { vv = s_vs[w][hh * KK + k]; break; }
                v[hh] = vv; vsum += vv;
            }
            float ewv = beta2;
#pragma unroll
            for (int c = 0; c < 8; c++) {
                float hid = s_eb1[c];
#pragma unroll
                for (int hh = 0; hh < HH; hh++) hid = fmaf(v[hh], s_ew1[hh * 8 + c], hid);
                hid = fmaxf(hid, 0.f);
                ewv = fmaf(hid, s_ew2[c], ewv);
            }
            float sig  = 1.f / (1.f + __expf(-ewv));
            float favv = sig * (vsum * 0.25f);
            g_Ah[(size_t)j * KP + i] = __float2half_rn(favv);   // A[m=j][k=i]
            fa[(size_t)i * NN + j] = favv;
        }
    }
}

// ---------------- 3: B = fp16( xr @ W ) transposed to [n=(bl,d)][k=i] ----------------
#define XS 68
__global__ __launch_bounds__(128) void support_b_kernel(
    const float* __restrict__ x, const float* __restrict__ W)
{
    __shared__ float xs[64 * XS];
    __shared__ float wt[64 * XS];
    __shared__ __half st[64 * 72];
    int tid = threadIdx.x;
    int bl = blockIdx.x >> 5;           // 0..127
    int i0 = (blockIdx.x & 31) * 64;    // 0..1984
    int b = bl >> 5, l = bl & 31;

    for (int k = tid; k < 1024; k += 128) {
        int d = k >> 4, o4 = (k & 15) * 4;
        float4 w = ((const float4*)W)[k];
        wt[(o4 + 0) * XS + d] = w.x;
        wt[(o4 + 1) * XS + d] = w.y;
        wt[(o4 + 2) * XS + d] = w.z;
        wt[(o4 + 3) * XS + d] = w.w;
    }
    for (int k = tid; k < 1024; k += 128) {
        int rr = k >> 4, f4 = k & 15;
        int i = i0 + rr;
        float4 v = make_float4(0.f, 0.f, 0.f, 0.f);
        if (i < NN)
            v = ((const float4*)(x + (((size_t)(b * NN + i) * 32) + l) * 64))[f4];
        *(float4*)&xs[rr * XS + f4 * 4] = v;
    }
    __syncthreads();

    int tr = tid & 7, tc = tid >> 3;
    float acc[8][4];
#pragma unroll
    for (int i = 0; i < 8; i++)
#pragma unroll
        for (int j = 0; j < 4; j++) acc[i][j] = 0.f;

#pragma unroll 4
    for (int d4 = 0; d4 < 64; d4 += 4) {
        float4 xv[8], wv[4];
#pragma unroll
        for (int i = 0; i < 8; i++) xv[i] = *(const float4*)&xs[(tr + 8 * i) * XS + d4];
#pragma unroll
        for (int j = 0; j < 4; j++) wv[j] = *(const float4*)&wt[(tc * 4 + j) * XS + d4];
#pragma unroll
        for (int i = 0; i < 8; i++)
#pragma unroll
            for (int j = 0; j < 4; j++) {
                acc[i][j] = fmaf(xv[i].x, wv[j].x, acc[i][j]);
                acc[i][j] = fmaf(xv[i].y, wv[j].y, acc[i][j]);
                acc[i][j] = fmaf(xv[i].z, wv[j].z, acc[i][j]);
                acc[i][j] = fmaf(xv[i].w, wv[j].w, acc[i][j]);
            }
    }

#pragma unroll
    for (int ri = 0; ri < 8; ri++)
#pragma unroll
        for (int j = 0; j < 4; j++)
            st[(tc * 4 + j) * 72 + (tr + 8 * ri)] = __float2half_rn(acc[ri][j]);
    __syncthreads();

    int d = tid >> 1, seg = tid & 1;
    const uint4* src = (const uint4*)((const char*)st + d * 144 + seg * 64);
    uint4* dst = (uint4*)(g_Bh + ((size_t)(bl * 64 + d)) * KP + i0 + seg * 32);
    dst[0] = src[0]; dst[1] = src[1]; dst[2] = src[2]; dst[3] = src[3];
}

// ---------------- 4: HMMA GEMM  C[m=c][n=(bl,d)] = A·B^T, +bias -> out ----------------
// 128x128 block tile, BK=64, 3-stage cp.async, 8 warps (2m x 4n), warp tile 64x32
static constexpr int GEMM_SMEM = 256 + 3 * STAGE_BYTES;   // 110848

__global__ __launch_bounds__(256, 1) void gemm_kernel(
    const float* __restrict__ bias, float* __restrict__ out)
{
    extern __shared__ char smem[];
    float* bs = (float*)smem;
    uint32_t tiles_u = smem_u32(smem + 256);
    int tid = threadIdx.x, wid = tid >> 5, lane = tid & 31;
    int m0 = (blockIdx.x & 15) * 128;
    int n0 = (blockIdx.x >> 4) * 128;

    if (tid < 64) bs[tid] = bias[tid];

    const __half* Ag = g_Ah + (size_t)m0 * KP;
    const __half* Bg = g_Bh + (size_t)n0 * KP;

#define LOAD_STAGE(c) do { \
        int _s = (c) % 3; \
        uint32_t _ab = tiles_u + _s * STAGE_BYTES; \
        uint32_t _bb = _ab + STAGE_BYTES / 2; \
        _Pragma("unroll") \
        for (int _u = 0; _u < 4; _u++) { \
            int _idx = tid * 4 + _u; \
            int _r = _idx >> 3, _q = _idx & 7; \
            uint32_t _off = (uint32_t)(_r * AST + _q * 8) * 2; \
            CPA16(_ab + _off, (const char*)(Ag + (size_t)_r * KP + (c) * BK + _q * 8)); \
            CPA16(_bb + _off, (const char*)(Bg + (size_t)_r * KP + (c) * BK + _q * 8)); \
        } \
        asm volatile("cp.async.commit_group;" ::: "memory"); \
    } while (0)

    LOAD_STAGE(0); LOAD_STAGE(1);

    int wm = wid >> 2, wn = wid & 3;
    float acc[4][4][4];
#pragma unroll
    for (int mi = 0; mi < 4; mi++)
#pragma unroll
        for (int nj = 0; nj < 4; nj++)
#pragma unroll
            for (int r = 0; r < 4; r++) acc[mi][nj][r] = 0.f;

    // ldmatrix lane address components
    int a_row = wm * 64 + (lane & 15);
    int a_koff = (lane >> 4) * 8;
    int b_grp = lane >> 3, b_idx = lane & 7;
    int b_nn_base = wn * 32 + (b_grp >> 1) * 8 + b_idx;
    int b_koff = (b_grp & 1) * 8;

    for (int c = 0; c < NCHUNK; c++) {
        if (c < NCHUNK - 1) asm volatile("cp.async.wait_group 1;" ::: "memory");
        else                asm volatile("cp.async.wait_group 0;" ::: "memory");
        __syncthreads();
        int s = c % 3;
        uint32_t ab = tiles_u + s * STAGE_BYTES;
        uint32_t bb = ab + STAGE_BYTES / 2;

#pragma unroll
        for (int ks = 0; ks < 4; ks++) {
            int k = ks * 16;
            uint32_t af[4][4];
#pragma unroll
            for (int mi = 0; mi < 4; mi++) {
                uint32_t addr = ab + (uint32_t)((a_row + mi * 16) * AST + k + a_koff) * 2;
                asm volatile("ldmatrix.sync.aligned.m8n8.x4.shared.b16 {%0,%1,%2,%3}, [%4];"
                    : "=r"(af[mi][0]), "=r"(af[mi][1]), "=r"(af[mi][2]), "=r"(af[mi][3]) : "r"(addr));
            }
            uint32_t bf[2][4];
#pragma unroll
            for (int np = 0; np < 2; np++) {
                uint32_t addr = bb + (uint32_t)((b_nn_base + np * 16) * AST + k + b_koff) * 2;
                asm volatile("ldmatrix.sync.aligned.m8n8.x4.shared.b16 {%0,%1,%2,%3}, [%4];"
                    : "=r"(bf[np][0]), "=r"(bf[np][1]), "=r"(bf[np][2]), "=r"(bf[np][3]) : "r"(addr));
            }
#pragma unroll
            for (int mi = 0; mi < 4; mi++)
#pragma unroll
                for (int nj = 0; nj < 4; nj++) {
                    uint32_t b0 = bf[nj >> 1][(nj & 1) * 2];
                    uint32_t b1 = bf[nj >> 1][(nj & 1) * 2 + 1];
                    asm volatile(
                        "mma.sync.aligned.m16n8k16.row.col.f32.f16.f16.f32 "
                        "{%0,%1,%2,%3}, {%4,%5,%6,%7}, {%8,%9}, {%0,%1,%2,%3};"
                        : "+f"(acc[mi][nj][0]), "+f"(acc[mi][nj][1]),
                          "+f"(acc[mi][nj][2]), "+f"(acc[mi][nj][3])
                        : "r"(af[mi][0]), "r"(af[mi][1]), "r"(af[mi][2]), "r"(af[mi][3]),
                          "r"(b0), "r"(b1));
                }
        }
        __syncthreads();
        if (c + 2 < NCHUNK) LOAD_STAGE(c + 2);
    }

    // epilogue: acc -> out[((b*NN + c)*32 + l)*64 + d] + bias[d]
#pragma unroll
    for (int nj = 0; nj < 4; nj++) {
        int n = n0 + wn * 32 + nj * 8 + (lane & 3) * 2;
        int bl = n >> 6;
        int b = bl >> 5, l = bl & 31;
        int d = n & 63;
        float b0 = bs[d], b1 = bs[d + 1];
#pragma unroll
        for (int mi = 0; mi < 4; mi++) {
            int r0 = m0 + wm * 64 + mi * 16 + (lane >> 2);
            if (r0 < NN) {
                float2 v; v.x = acc[mi][nj][0] + b0; v.y = acc[mi][nj][1] + b1;
                *(float2*)(out + ((size_t)(b * NN + r0) * 32 + l) * 64 + d) = v;
            }
            int r1 = r0 + 8;
            if (r1 < NN) {
                float2 v; v.x = acc[mi][nj][2] + b0; v.y = acc[mi][nj][3] + b1;
                *(float2*)(out + ((size_t)(b * NN + r1) * 32 + l) * 64 + d) = v;
            }
        }
    }
}

// ---------------- launch ----------------
extern "C" void kernel_launch(void* const* d_in, const int* in_sizes, int n_in,
                              void* d_out, int out_size)
{
    const float* x      = (const float*)d_in[0];
    const float* e1     = (const float*)d_in[1];
    const float* e2     = (const float*)d_in[2];
    const float* temp   = (const float*)d_in[3];
    const float* ew1    = (const float*)d_in[4];
    const float* eb1    = (const float*)d_in[5];
    const float* ew2    = (const float*)d_in[6];
    const float* eb2    = (const float*)d_in[7];
    const float* weight = (const float*)d_in[8];
    const float* bias   = (const float*)d_in[9];
    float* out = (float*)d_out;

    float* fa;
    if (out_size >= OUT_ELEMS + NN * NN) {
        fa = out + OUT_ELEMS;
    } else {
        void* p = nullptr;
        cudaGetSymbolAddress(&p, g_fa_fb);
        fa = (float*)p;
    }

    const int smem_scores = (TILE * NN + TILE * NDm) * sizeof(float);
    cudaFuncSetAttribute(scores_topk_kernel,
                         cudaFuncAttributeMaxDynamicSharedMemorySize, smem_scores);
    cudaFuncSetAttribute(gemm_kernel,
                         cudaFuncAttributeMaxDynamicSharedMemorySize, GEMM_SMEM);

    zero_kernel<<<2048, 256>>>(fa);
    scores_topk_kernel<<<HH * (NN / TILE), 256, smem_scores>>>(e1, e2, temp);
    build_rows_kernel<<<NN / 8, 256>>>(ew1, eb1, ew2, eb2, fa);
    support_b_kernel<<<BLT * 32, 128>>>(x, weight);
    gemm_kernel<<<(MP / 128) * (NTOT / 128), 256, GEMM_SMEM>>>(bias, out);
}

// round 8
// speedup vs baseline: 1.2687x; 1.2687x over previous
#include <cuda_runtime.h>
#include <cuda_fp16.h>
#include <cstdint>

#define NN   2000
#define HH   4
#define NDm  64
#define KK   20
#define TILE 8
#define BLT  128          // B*L = 4*32
#define DD   64
#define OUT_ELEMS (4*2000*32*64)
#define CCAP 512          // per-column entry capacity

// ---------------- scratch (device globals; no allocation) ----------------
__device__ __align__(16) __half g_supph[(size_t)BLT*NN*DD];   // 32.8 MB fp16 support
__device__ int   g_tki[HH*NN*KK];
__device__ float g_tkv[HH*NN*KK];
__device__ int   g_colcnt[NN];
__device__ int   g_ci[(size_t)NN*CCAP];
__device__ float g_cv[(size_t)NN*CCAP];
__device__ float g_fa_fb[(size_t)NN*NN];         // fallback final_adj (16 MB)

// ---------------- 0: zero counters + final_adj region ----------------
__global__ void zero_kernel(float* fa) {
    int idx = blockIdx.x * blockDim.x + threadIdx.x;
    if (idx < NN) g_colcnt[idx] = 0;
    size_t stride = (size_t)gridDim.x * blockDim.x;
    for (size_t p = idx; p < (size_t)NN * NN; p += stride) fa[p] = 0.f;
}

// ---------------- 1: scores + top-20 (softmax-S dropped: <=2e-5 rel effect) ----------------
// grid = H * (N/TILE) blocks, 256 threads (8 warps; warp w owns row n0+w)
__global__ __launch_bounds__(256) void scores_topk_kernel(
    const float* __restrict__ e1, const float* __restrict__ e2,
    const float* __restrict__ temp)
{
    extern __shared__ float sm[];
    float* s   = sm;                // [TILE][NN] transformed scores a = relu(s)/T
    float* e1s = sm + TILE * NN;    // [TILE][NDm]

    int h  = blockIdx.x / (NN / TILE);
    int n0 = (blockIdx.x % (NN / TILE)) * TILE;
    int tid = threadIdx.x;
    float invT = 1.0f / temp[h];

    for (int i = tid; i < TILE * NDm; i += blockDim.x)
        e1s[i] = e1[((size_t)h * NN + n0 + i / NDm) * NDm + (i % NDm)];
    __syncthreads();

    for (int m = tid; m < NN; m += blockDim.x) {
        float acc[TILE];
#pragma unroll
        for (int r = 0; r < TILE; r++) acc[r] = 0.f;
        const float* e2p = e2 + (size_t)h * NDm * NN + m;
#pragma unroll 8
        for (int d = 0; d < NDm; d++) {
            float b = e2p[(size_t)d * NN];
#pragma unroll
            for (int r = 0; r < TILE; r++) acc[r] = fmaf(e1s[r * NDm + d], b, acc[r]);
        }
#pragma unroll
        for (int r = 0; r < TILE; r++) s[r * NN + m] = fmaxf(acc[r], 0.f) * invT;
    }
    __syncthreads();

    int w = tid >> 5, lane = tid & 31;
    float* sw = s + w * NN;

    // per-lane local max over its strided strip (values >= 0; -1 marks taken)
    float lmax = -1.f; int lm = lane;
    for (int m = lane; m < NN; m += 32) {
        float v = sw[m];
        if (v > lmax) { lmax = v; lm = m; }
    }

    int base = (h * NN + n0 + w) * KK;
    float M = 0.f, ssel = 0.f;
    for (int k = 0; k < KK; k++) {
        float best = lmax; int bm = lm;
#pragma unroll
        for (int o = 16; o; o >>= 1) {
            float ov = __shfl_xor_sync(0xffffffffu, best, o);
            int   oi = __shfl_xor_sync(0xffffffffu, bm,   o);
            if (ov > best || (ov == best && oi < bm)) { best = ov; bm = oi; }
        }
        if (k == 0) M = best;              // first pick is the row max
        float e = __expf(best - M);
        ssel += e;                          // identical on all lanes
        if (lane == 0) { g_tki[base + k] = bm; g_tkv[base + k] = e; }
        if ((bm & 31) == lane) {            // winner lane: mark + rescan its strip
            sw[bm] = -1.f;
            lmax = -1.f; lm = lane;
            for (int m = lane; m < NN; m += 32) {
                float v = sw[m];
                if (v > lmax) { lmax = v; lm = m; }
            }
        }
        __syncwarp();
    }
    if (lane < KK) g_tkv[base + lane] = g_tkv[base + lane] / ssel;
}

// ---------------- 2: per-row union + edge MLP -> column lists + dense fa ----------------
// one warp per row i; grid = N/8 blocks of 256 threads
__global__ __launch_bounds__(256) void build_rows_kernel(
    const float* __restrict__ ew1, const float* __restrict__ eb1,
    const float* __restrict__ ew2, const float* __restrict__ eb2,
    float* __restrict__ fa)
{
    __shared__ float s_ew1[HH * 8];
    __shared__ float s_eb1[8];
    __shared__ float s_ew2[8];
    __shared__ int   s_js[8][80];
    __shared__ float s_vs[8][80];

    int tid = threadIdx.x;
    if (tid < 32) s_ew1[tid] = ew1[tid];
    else if (tid < 40) s_eb1[tid - 32] = eb1[tid - 32];
    else if (tid < 48) s_ew2[tid - 40] = ew2[tid - 40];
    float beta2 = eb2[0];
    __syncthreads();

    int w = tid >> 5, lane = tid & 31;
    int i = blockIdx.x * 8 + w;

    for (int e = lane; e < 80; e += 32) {
        int hh = e / KK, k = e % KK;
        s_js[w][e] = g_tki[(hh * NN + i) * KK + k];
        s_vs[w][e] = g_tkv[(hh * NN + i) * KK + k];
    }
    __syncwarp();

    for (int p = 0; p < 3; p++) {
        int e = lane + p * 32;
        bool owned = false;
        int j = -1;
        if (e < 80) {
            j = s_js[w][e];
            owned = true;
            for (int q = 0; q < e; q++)
                if (s_js[w][q] == j) { owned = false; break; }
        }
        if (owned) {
            float v[HH];
            float vsum = 0.f;
#pragma unroll
            for (int hh = 0; hh < HH; hh++) {
                float vv = 0.f;
                for (int k = 0; k < KK; k++)
                    if (s_js[w][hh * KK + k] == j) { vv = s_vs[w][hh * KK + k]; break; }
                v[hh] = vv; vsum += vv;
            }
            float ewv = beta2;
#pragma unroll
            for (int c = 0; c < 8; c++) {
                float hid = s_eb1[c];
#pragma unroll
                for (int hh = 0; hh < HH; hh++) hid = fmaf(v[hh], s_ew1[hh * 8 + c], hid);
                hid = fmaxf(hid, 0.f);
                ewv = fmaf(hid, s_ew2[c], ewv);
            }
            float sig  = 1.f / (1.f + __expf(-ewv));
            float favv = sig * (vsum * 0.25f);
            int pos = atomicAdd(&g_colcnt[j], 1);
            if (pos < CCAP) {
                g_ci[(size_t)j * CCAP + pos] = i;
                g_cv[(size_t)j * CCAP + pos] = favv;
            }
            fa[(size_t)i * NN + j] = favv;
        }
    }
}

// ---------------- 3: support = fp16( xr @ W ), register-blocked 64x64 tile ----------------
#define XS_STRIDE 68
__global__ __launch_bounds__(128) void support_kernel(
    const float* __restrict__ x, const float* __restrict__ W)
{
    __shared__ float xs[64 * XS_STRIDE];
    __shared__ float wt[64 * XS_STRIDE];
    int tid = threadIdx.x;

    for (int k = tid; k < 1024; k += 128) {
        int d = k >> 4, o4 = (k & 15) * 4;
        float4 w = ((const float4*)W)[k];
        wt[(o4 + 0) * XS_STRIDE + d] = w.x;
        wt[(o4 + 1) * XS_STRIDE + d] = w.y;
        wt[(o4 + 2) * XS_STRIDE + d] = w.z;
        wt[(o4 + 3) * XS_STRIDE + d] = w.w;
    }
    int row0 = blockIdx.x * 64;
    for (int k = tid; k < 1024; k += 128) {
        int rr = k >> 4, f4 = k & 15;
        int r = row0 + rr;
        int bl = r / NN, n = r - bl * NN;
        int b = bl >> 5, l = bl & 31;
        float4 v = ((const float4*)(x + (((size_t)(b * NN + n) * 32) + l) * 64))[f4];
        *(float4*)&xs[rr * XS_STRIDE + f4 * 4] = v;
    }
    __syncthreads();

    int tr = tid & 7, to = tid >> 3;
    float acc[8][4];
#pragma unroll
    for (int i = 0; i < 8; i++)
#pragma unroll
        for (int j = 0; j < 4; j++) acc[i][j] = 0.f;

#pragma unroll 4
    for (int d4 = 0; d4 < 64; d4 += 4) {
        float4 xv[8], wv[4];
#pragma unroll
        for (int i = 0; i < 8; i++) xv[i] = *(const float4*)&xs[(tr + 8 * i) * XS_STRIDE + d4];
#pragma unroll
        for (int j = 0; j < 4; j++) wv[j] = *(const float4*)&wt[(to * 4 + j) * XS_STRIDE + d4];
#pragma unroll
        for (int i = 0; i < 8; i++)
#pragma unroll
            for (int j = 0; j < 4; j++) {
                acc[i][j] = fmaf(xv[i].x, wv[j].x, acc[i][j]);
                acc[i][j] = fmaf(xv[i].y, wv[j].y, acc[i][j]);
                acc[i][j] = fmaf(xv[i].z, wv[j].z, acc[i][j]);
                acc[i][j] = fmaf(xv[i].w, wv[j].w, acc[i][j]);
            }
    }

#pragma unroll
    for (int i = 0; i < 8; i++) {
        int r = row0 + tr + 8 * i;
        __half2 h0 = __floats2half2_rn(acc[i][0], acc[i][1]);
        __half2 h1 = __floats2half2_rn(acc[i][2], acc[i][3]);
        uint2 pk;
        pk.x = *(uint32_t*)&h0;
        pk.y = *(uint32_t*)&h1;
        *(uint2*)(g_supph + (size_t)r * 64 + to * 4) = pk;
    }
}

// ---------------- 4: sparse out[b,c,l,:] = sum_e w_e * support[bl, j_e, :] + bias ----------------
// one block per column c; 256 threads = 8 d-octets x 32 bl-groups; 4 bl iters
__global__ __launch_bounds__(256) void spmm_kernel(
    const float* __restrict__ bias, float* __restrict__ out)
{
    __shared__ int   sj[CCAP];
    __shared__ float sv[CCAP];
    int c = blockIdx.x;
    int tid = threadIdx.x;
    int q = tid & 7;        // d octet: d = 8q .. 8q+7
    int g = tid >> 3;       // 0..31
    int cnt = g_colcnt[c];
    if (cnt > CCAP) cnt = CCAP;
    size_t start = (size_t)c * CCAP;

    float acc[4][8];
#pragma unroll
    for (int it = 0; it < 4; it++)
#pragma unroll
        for (int j = 0; j < 8; j++) acc[it][j] = 0.f;

    const uint4* supp4 = (const uint4*)g_supph;   // 8 halves per uint4

    for (int e = tid; e < cnt; e += 256) {
        sj[e] = g_ci[start + e];
        sv[e] = g_cv[start + e];
    }
    __syncthreads();
    for (int e = 0; e < cnt; e++) {
        float wv = sv[e];
        int   i  = sj[e];
#pragma unroll
        for (int it = 0; it < 4; it++) {
            int bl = it * 32 + g;
            uint4 h4 = supp4[(size_t)(bl * NN + i) * 8 + q];
            const __half2* hh = (const __half2*)&h4;
#pragma unroll
            for (int j = 0; j < 4; j++) {
                float2 f = __half22float2(hh[j]);
                acc[it][2 * j]     = fmaf(wv, f.x, acc[it][2 * j]);
                acc[it][2 * j + 1] = fmaf(wv, f.y, acc[it][2 * j + 1]);
            }
        }
    }

    float bv[8];
#pragma unroll
    for (int j = 0; j < 8; j++) bv[j] = bias[q * 8 + j];

#pragma unroll
    for (int it = 0; it < 4; it++) {
        int bl = it * 32 + g;
        int b = bl >> 5, l = bl & 31;
        float4 r0, r1;
        r0.x = acc[it][0] + bv[0]; r0.y = acc[it][1] + bv[1];
        r0.z = acc[it][2] + bv[2]; r0.w = acc[it][3] + bv[3];
        r1.x = acc[it][4] + bv[4]; r1.y = acc[it][5] + bv[5];
        r1.z = acc[it][6] + bv[6]; r1.w = acc[it][7] + bv[7];
        size_t ob = (size_t)((b * NN + c) * 32 + l) * 16 + q * 2;
        ((float4*)out)[ob]     = r0;
        ((float4*)out)[ob + 1] = r1;
    }
}

// ---------------- launch ----------------
extern "C" void kernel_launch(void* const* d_in, const int* in_sizes, int n_in,
                              void* d_out, int out_size)
{
    const float* x      = (const float*)d_in[0];
    const float* e1     = (const float*)d_in[1];
    const float* e2     = (const float*)d_in[2];
    const float* temp   = (const float*)d_in[3];
    const float* ew1    = (const float*)d_in[4];
    const float* eb1    = (const float*)d_in[5];
    const float* ew2    = (const float*)d_in[6];
    const float* eb2    = (const float*)d_in[7];
    const float* weight = (const float*)d_in[8];
    const float* bias   = (const float*)d_in[9];
    float* out = (float*)d_out;

    // final_adj destination: appended after out if there is room, else fallback scratch
    float* fa;
    if (out_size >= OUT_ELEMS + NN * NN) {
        fa = out + OUT_ELEMS;
    } else {
        void* p = nullptr;
        cudaGetSymbolAddress(&p, g_fa_fb);
        fa = (float*)p;
    }

    const int smem_scores = (TILE * NN + TILE * NDm) * sizeof(float);  // ~66 KB
    cudaFuncSetAttribute(scores_topk_kernel,
                         cudaFuncAttributeMaxDynamicSharedMemorySize, smem_scores);

    zero_kernel<<<2048, 256>>>(fa);
    scores_topk_kernel<<<HH * (NN / TILE), 256, smem_scores>>>(e1, e2, temp);
    build_rows_kernel<<<NN / 8, 256>>>(ew1, eb1, ew2, eb2, fa);
    support_kernel<<<(BLT * NN) / 64, 128>>>(x, weight);
    spmm_kernel<<<NN, 256>>>(bias, out);
}

// round 9
// speedup vs baseline: 1.4898x; 1.1743x over previous
#include <cuda_runtime.h>
#include <cuda_fp16.h>
#include <cstdint>

#define NN   2000
#define HH   4
#define NDm  64
#define KK   20
#define TILE 8
#define BLT  128          // B*L = 4*32
#define DD   64
#define OUT_ELEMS (4*2000*32*64)
#define NNZ_CAP   (NN*80)

// ---------------- scratch (device globals; no allocation) ----------------
__device__ __align__(16) __half g_supph[(size_t)BLT*NN*DD];   // 32.8 MB fp16 support
__device__ int   g_tki[HH*NN*KK];
__device__ float g_tkv[HH*NN*KK];
__device__ int   g_rowj[NN*80];
__device__ float g_rowv[NN*80];
__device__ int   g_rowcnt[NN];
__device__ int   g_colcnt[NN];
__device__ int   g_colptr[NN];
__device__ int   g_colcur[NN];
__device__ int   g_ci[NNZ_CAP];
__device__ float g_cv[NNZ_CAP];
__device__ float g_fa_fb[(size_t)NN*NN];         // fallback final_adj (16 MB)

// ---------------- 0: zero counters + final_adj region ----------------
__global__ void zero_kernel(float* fa) {
    int idx = blockIdx.x * blockDim.x + threadIdx.x;
    if (idx < NN) g_colcnt[idx] = 0;
    size_t stride = (size_t)gridDim.x * blockDim.x;
    for (size_t p = idx; p < (size_t)NN * NN; p += stride) fa[p] = 0.f;
}

// ---------------- 1: scores + top-20 (softmax-S term dropped: <=2e-5 rel effect) ----------------
// grid = H * (N/TILE) blocks, 256 threads (8 warps; warp w owns row n0+w)
__global__ __launch_bounds__(256) void scores_topk_kernel(
    const float* __restrict__ e1, const float* __restrict__ e2,
    const float* __restrict__ temp)
{
    extern __shared__ float sm[];
    float* s   = sm;                // [TILE][NN]
    float* e1s = sm + TILE * NN;    // [TILE][NDm]

    int h  = blockIdx.x / (NN / TILE);
    int n0 = (blockIdx.x % (NN / TILE)) * TILE;
    int tid = threadIdx.x;

    for (int i = tid; i < TILE * NDm; i += blockDim.x)
        e1s[i] = e1[((size_t)h * NN + n0 + i / NDm) * NDm + (i % NDm)];
    __syncthreads();

    for (int m = tid; m < NN; m += blockDim.x) {
        float acc[TILE];
#pragma unroll
        for (int r = 0; r < TILE; r++) acc[r] = 0.f;
        const float* e2p = e2 + (size_t)h * NDm * NN + m;
#pragma unroll 8
        for (int d = 0; d < NDm; d++) {
            float b = e2p[(size_t)d * NN];
#pragma unroll
            for (int r = 0; r < TILE; r++) acc[r] = fmaf(e1s[r * NDm + d], b, acc[r]);
        }
#pragma unroll
        for (int r = 0; r < TILE; r++) s[r * NN + m] = acc[r];
    }
    __syncthreads();

    int w = tid >> 5, lane = tid & 31;
    float invT = 1.0f / temp[h];
    float* sw = s + w * NN;

    // relu + /temp in place; row max (all values >= 0). (No exp-sum pass: the
    // reference's 1e-8*S correction to the renorm denominator is <=2e-5 relative.)
    float M = 0.f;
    for (int m = lane; m < NN; m += 32) {
        float a = fmaxf(sw[m], 0.f) * invT;
        sw[m] = a;
        M = fmaxf(M, a);
    }
#pragma unroll
    for (int o = 16; o; o >>= 1) M = fmaxf(M, __shfl_xor_sync(0xffffffffu, M, o));

    int base = (h * NN + n0 + w) * KK;
    float ssel = 0.f;
    for (int k = 0; k < KK; k++) {
        float best = -1.f; int bi = NN;
        for (int m = lane; m < NN; m += 32) {
            float v = sw[m];
            if (v > best) { best = v; bi = m; }   // ascending m keeps lowest index on ties
        }
#pragma unroll
        for (int o = 16; o; o >>= 1) {
            float ov = __shfl_xor_sync(0xffffffffu, best, o);
            int   oi = __shfl_xor_sync(0xffffffffu, bi,   o);
            if (ov > best || (ov == best && oi < bi)) { best = ov; bi = oi; }
        }
        float e = __expf(best - M);
        ssel += e;                       // same on all lanes
        if (lane == 0) { g_tki[base + k] = bi; g_tkv[base + k] = e; }
        sw[bi] = -1.f;                   // mark taken (all lanes write same value)
        __syncwarp();
    }
    __syncwarp();
    if (lane < KK) g_tkv[base + lane] = g_tkv[base + lane] / ssel;
}

// ---------------- 2: per-row union + edge MLP -> sparse rows + dense fa ----------------
// one warp per row i; grid = N/8 blocks of 256 threads
__global__ __launch_bounds__(256) void build_rows_kernel(
    const float* __restrict__ ew1, const float* __restrict__ eb1,
    const float* __restrict__ ew2, const float* __restrict__ eb2,
    float* __restrict__ fa)
{
    __shared__ float s_ew1[HH * 8];
    __shared__ float s_eb1[8];
    __shared__ float s_ew2[8];
    __shared__ int   s_js[8][80];
    __shared__ float s_vs[8][80];

    int tid = threadIdx.x;
    if (tid < 32) s_ew1[tid] = ew1[tid];
    else if (tid < 40) s_eb1[tid - 32] = eb1[tid - 32];
    else if (tid < 48) s_ew2[tid - 40] = ew2[tid - 40];
    float beta2 = eb2[0];
    __syncthreads();

    int w = tid >> 5, lane = tid & 31;
    int i = blockIdx.x * 8 + w;

    for (int e = lane; e < 80; e += 32) {
        int hh = e / KK, k = e % KK;
        s_js[w][e] = g_tki[(hh * NN + i) * KK + k];
        s_vs[w][e] = g_tkv[(hh * NN + i) * KK + k];
    }
    __syncwarp();

    int cnt = 0;
    for (int p = 0; p < 3; p++) {
        int e = lane + p * 32;
        bool owned = false;
        int j = -1;
        if (e < 80) {
            j = s_js[w][e];
            owned = true;
            for (int q = 0; q < e; q++)
                if (s_js[w][q] == j) { owned = false; break; }
        }
        unsigned bal = __ballot_sync(0xffffffffu, owned);
        int pos = cnt + __popc(bal & ((1u << lane) - 1u));
        if (owned) {
            float v[HH];
            float vsum = 0.f;
#pragma unroll
            for (int hh = 0; hh < HH; hh++) {
                float vv = 0.f;
                for (int k = 0; k < KK; k++)
                    if (s_js[w][hh * KK + k] == j) { vv = s_vs[w][hh * KK + k]; break; }
                v[hh] = vv; vsum += vv;
            }
            float ewv = beta2;
#pragma unroll
            for (int c = 0; c < 8; c++) {
                float hid = s_eb1[c];
#pragma unroll
                for (int hh = 0; hh < HH; hh++) hid = fmaf(v[hh], s_ew1[hh * 8 + c], hid);
                hid = fmaxf(hid, 0.f);
                ewv = fmaf(hid, s_ew2[c], ewv);
            }
            float sig  = 1.f / (1.f + __expf(-ewv));
            float favv = sig * (vsum * 0.25f);
            g_rowj[i * 80 + pos] = j;
            g_rowv[i * 80 + pos] = favv;
            atomicAdd(&g_colcnt[j], 1);
            fa[(size_t)i * NN + j] = favv;
        }
        cnt += __popc(bal);
    }
    if (lane == 0) g_rowcnt[i] = cnt;
}

// ---------------- 3: exclusive scan over column counts (single block) ----------------
__global__ __launch_bounds__(1024) void scan_kernel() {
    __shared__ int buf[1024];
    int t = threadIdx.x;
    int c0 = (2 * t     < NN) ? g_colcnt[2 * t]     : 0;
    int c1 = (2 * t + 1 < NN) ? g_colcnt[2 * t + 1] : 0;
    int psum = c0 + c1;
    buf[t] = psum;
    __syncthreads();
    for (int off = 1; off < 1024; off <<= 1) {
        int tmp = (t >= off) ? buf[t - off] : 0;
        __syncthreads();
        buf[t] += tmp;
        __syncthreads();
    }
    int base = buf[t] - psum;   // exclusive
    if (2 * t < NN)     { g_colptr[2 * t]     = base;      g_colcur[2 * t]     = base; }
    if (2 * t + 1 < NN) { g_colptr[2 * t + 1] = base + c0; g_colcur[2 * t + 1] = base + c0; }
}

// ---------------- 4: fill transposed (per-column) entry lists ----------------
__global__ void fill_kernel() {
    int i = blockIdx.x;
    int t = threadIdx.x;
    int cnt = g_rowcnt[i];
    if (t < cnt) {
        int j = g_rowj[i * 80 + t];
        int pos = atomicAdd(&g_colcur[j], 1);
        g_ci[pos] = i;
        g_cv[pos] = g_rowv[i * 80 + t];
    }
}

// ---------------- 5: support = fp16( xr @ W ), register-blocked 64x64 tile ----------------
#define XS_STRIDE 68
__global__ __launch_bounds__(128) void support_kernel(
    const float* __restrict__ x, const float* __restrict__ W)
{
    __shared__ float xs[64 * XS_STRIDE];
    __shared__ float wt[64 * XS_STRIDE];
    int tid = threadIdx.x;

    for (int k = tid; k < 1024; k += 128) {
        int d = k >> 4, o4 = (k & 15) * 4;
        float4 w = ((const float4*)W)[k];
        wt[(o4 + 0) * XS_STRIDE + d] = w.x;
        wt[(o4 + 1) * XS_STRIDE + d] = w.y;
        wt[(o4 + 2) * XS_STRIDE + d] = w.z;
        wt[(o4 + 3) * XS_STRIDE + d] = w.w;
    }
    int row0 = blockIdx.x * 64;
    for (int k = tid; k < 1024; k += 128) {
        int rr = k >> 4, f4 = k & 15;
        int r = row0 + rr;
        int bl = r / NN, n = r - bl * NN;
        int b = bl >> 5, l = bl & 31;
        float4 v = ((const float4*)(x + (((size_t)(b * NN + n) * 32) + l) * 64))[f4];
        *(float4*)&xs[rr * XS_STRIDE + f4 * 4] = v;
    }
    __syncthreads();

    int tr = tid & 7, to = tid >> 3;
    float acc[8][4];
#pragma unroll
    for (int i = 0; i < 8; i++)
#pragma unroll
        for (int j = 0; j < 4; j++) acc[i][j] = 0.f;

#pragma unroll 4
    for (int d4 = 0; d4 < 64; d4 += 4) {
        float4 xv[8], wv[4];
#pragma unroll
        for (int i = 0; i < 8; i++) xv[i] = *(const float4*)&xs[(tr + 8 * i) * XS_STRIDE + d4];
#pragma unroll
        for (int j = 0; j < 4; j++) wv[j] = *(const float4*)&wt[(to * 4 + j) * XS_STRIDE + d4];
#pragma unroll
        for (int i = 0; i < 8; i++)
#pragma unroll
            for (int j = 0; j < 4; j++) {
                acc[i][j] = fmaf(xv[i].x, wv[j].x, acc[i][j]);
                acc[i][j] = fmaf(xv[i].y, wv[j].y, acc[i][j]);
                acc[i][j] = fmaf(xv[i].z, wv[j].z, acc[i][j]);
                acc[i][j] = fmaf(xv[i].w, wv[j].w, acc[i][j]);
            }
    }

#pragma unroll
    for (int i = 0; i < 8; i++) {
        int r = row0 + tr + 8 * i;
        __half2 h0 = __floats2half2_rn(acc[i][0], acc[i][1]);
        __half2 h1 = __floats2half2_rn(acc[i][2], acc[i][3]);
        uint2 pk;
        pk.x = *(uint32_t*)&h0;
        pk.y = *(uint32_t*)&h1;
        *(uint2*)(g_supph + (size_t)r * 64 + to * 4) = pk;
    }
}

// ---------------- 6: sparse out[b,c,l,:] = sum_e w_e * support[bl, j_e, :] + bias ----------------
// one block per column c; 256 threads = 8 d-octets x 32 bl-groups; 4 bl iters
__global__ __launch_bounds__(256) void spmm_kernel(
    const float* __restrict__ bias, float* __restrict__ out)
{
    __shared__ int   sj[512];
    __shared__ float sv[512];
    int c = blockIdx.x;
    int tid = threadIdx.x;
    int q = tid & 7;        // d octet: d = 8q .. 8q+7
    int g = tid >> 3;       // 0..31
    int start = g_colptr[c], cnt = g_colcnt[c];

    float acc[4][8];
#pragma unroll
    for (int it = 0; it < 4; it++)
#pragma unroll
        for (int j = 0; j < 8; j++) acc[it][j] = 0.f;

    const uint4* supp4 = (const uint4*)g_supph;   // 8 halves per uint4

    for (int off = 0; off < cnt; off += 512) {
        int chunk = min(512, cnt - off);
        for (int e = tid; e < chunk; e += 256) {
            sj[e] = g_ci[start + off + e];
            sv[e] = g_cv[start + off + e];
        }
        __syncthreads();
        for (int e = 0; e < chunk; e++) {
            float wv = sv[e];
            int   i  = sj[e];
#pragma unroll
            for (int it = 0; it < 4; it++) {
                int bl = it * 32 + g;
                uint4 h4 = supp4[(size_t)(bl * NN + i) * 8 + q];
                const __half2* hh = (const __half2*)&h4;
#pragma unroll
                for (int j = 0; j < 4; j++) {
                    float2 f = __half22float2(hh[j]);
                    acc[it][2 * j]     = fmaf(wv, f.x, acc[it][2 * j]);
                    acc[it][2 * j + 1] = fmaf(wv, f.y, acc[it][2 * j + 1]);
                }
            }
        }
        __syncthreads();
    }

    float bv[8];
#pragma unroll
    for (int j = 0; j < 8; j++) bv[j] = bias[q * 8 + j];

#pragma unroll
    for (int it = 0; it < 4; it++) {
        int bl = it * 32 + g;
        int b = bl >> 5, l = bl & 31;
        float4 r0, r1;
        r0.x = acc[it][0] + bv[0]; r0.y = acc[it][1] + bv[1];
        r0.z = acc[it][2] + bv[2]; r0.w = acc[it][3] + bv[3];
        r1.x = acc[it][4] + bv[4]; r1.y = acc[it][5] + bv[5];
        r1.z = acc[it][6] + bv[6]; r1.w = acc[it][7] + bv[7];
        size_t ob = (size_t)((b * NN + c) * 32 + l) * 16 + q * 2;
        ((float4*)out)[ob]     = r0;
        ((float4*)out)[ob + 1] = r1;
    }
}

// ---------------- launch ----------------
extern "C" void kernel_launch(void* const* d_in, const int* in_sizes, int n_in,
                              void* d_out, int out_size)
{
    const float* x      = (const float*)d_in[0];
    const float* e1     = (const float*)d_in[1];
    const float* e2     = (const float*)d_in[2];
    const float* temp   = (const float*)d_in[3];
    const float* ew1    = (const float*)d_in[4];
    const float* eb1    = (const float*)d_in[5];
    const float* ew2    = (const float*)d_in[6];
    const float* eb2    = (const float*)d_in[7];
    const float* weight = (const float*)d_in[8];
    const float* bias   = (const float*)d_in[9];
    float* out = (float*)d_out;

    // final_adj destination: appended after out if there is room, else fallback scratch
    float* fa;
    if (out_size >= OUT_ELEMS + NN * NN) {
        fa = out + OUT_ELEMS;
    } else {
        void* p = nullptr;
        cudaGetSymbolAddress(&p, g_fa_fb);
        fa = (float*)p;
    }

    const int smem_scores = (TILE * NN + TILE * NDm) * sizeof(float);  // ~66 KB
    cudaFuncSetAttribute(scores_topk_kernel,
                         cudaFuncAttributeMaxDynamicSharedMemorySize, smem_scores);

    zero_kernel<<<2048, 256>>>(fa);
    scores_topk_kernel<<<HH * (NN / TILE), 256, smem_scores>>>(e1, e2, temp);
    build_rows_kernel<<<NN / 8, 256>>>(ew1, eb1, ew2, eb2, fa);
    scan_kernel<<<1, 1024>>>();
    fill_kernel<<<NN, 96>>>();
    support_kernel<<<(BLT * NN) / 64, 128>>>(x, weight);
    spmm_kernel<<<NN, 256>>>(bias, out);
}

// round 10
// speedup vs baseline: 1.5394x; 1.0333x over previous
#include <cuda_runtime.h>
#include <cuda_fp16.h>
#include <cstdint>

#define NN   2000
#define HH   4
#define NDm  64
#define KK   20
#define TILE 8
#define BLT  128          // B*L = 4*32
#define DD   64
#define OUT_ELEMS (4*2000*32*64)
#define NNZ_CAP   (NN*80)
#define MARKV (-3.0e38f)

// ---------------- scratch (device globals; no allocation) ----------------
__device__ __align__(16) __half g_supph[(size_t)BLT*NN*DD];   // 32.8 MB fp16 support
__device__ int   g_tki[HH*NN*KK];
__device__ float g_tkv[HH*NN*KK];
__device__ int   g_rowj[NN*80];
__device__ float g_rowv[NN*80];
__device__ int   g_rowcnt[NN];
__device__ int   g_colcnt[NN];
__device__ int   g_colptr[NN];
__device__ int   g_colcur[NN];
__device__ int   g_ci[NNZ_CAP];
__device__ float g_cv[NNZ_CAP];
__device__ float g_fa_fb[(size_t)NN*NN];         // fallback final_adj (16 MB)

// ---------------- 0: zero counters + final_adj region ----------------
__global__ void zero_kernel(float* fa) {
    int idx = blockIdx.x * blockDim.x + threadIdx.x;
    if (idx < NN) g_colcnt[idx] = 0;
    size_t stride = (size_t)gridDim.x * blockDim.x;
    for (size_t p = idx; p < (size_t)NN * NN; p += stride) fa[p] = 0.f;
}

// ---------------- 1: scores + top-20 via per-lane top-4 candidates ----------------
// grid = H * (N/TILE) blocks, 256 threads (8 warps; warp w owns row n0+w).
// Exact: consumed entries are marked in smem; a lane that exhausts its 4
// candidates rescans its own strip (rare). Softmax-S term dropped (<=2e-5 rel).
__global__ __launch_bounds__(256) void scores_topk_kernel(
    const float* __restrict__ e1, const float* __restrict__ e2,
    const float* __restrict__ temp)
{
    extern __shared__ float sm[];
    float* s   = sm;                // [TILE][NN] raw scores
    float* e1s = sm + TILE * NN;    // [TILE][NDm]

    int h  = blockIdx.x / (NN / TILE);
    int n0 = (blockIdx.x % (NN / TILE)) * TILE;
    int tid = threadIdx.x;

    for (int i = tid; i < TILE * NDm; i += blockDim.x)
        e1s[i] = e1[((size_t)h * NN + n0 + i / NDm) * NDm + (i % NDm)];
    __syncthreads();

    for (int m = tid; m < NN; m += blockDim.x) {
        float acc[TILE];
#pragma unroll
        for (int r = 0; r < TILE; r++) acc[r] = 0.f;
        const float* e2p = e2 + (size_t)h * NDm * NN + m;
#pragma unroll 8
        for (int d = 0; d < NDm; d++) {
            float b = e2p[(size_t)d * NN];
#pragma unroll
            for (int r = 0; r < TILE; r++) acc[r] = fmaf(e1s[r * NDm + d], b, acc[r]);
        }
#pragma unroll
        for (int r = 0; r < TILE; r++) s[r * NN + m] = acc[r];   // raw
    }
    __syncthreads();

    int w = tid >> 5, lane = tid & 31;
    float invT = 1.0f / temp[h];
    float* sw = s + w * NN;

    // per-lane sorted top-4 of transformed strip (strict > keeps lowest index on ties)
    float v0 = -1.f, v1 = -1.f, v2 = -1.f, v3 = -1.f;
    int   m0 = 0,    m1 = 0,    m2 = 0,    m3 = 0;
#define INSERT_CAND(a, m) do { \
        if ((a) > v3) { \
            if ((a) > v0)      { v3=v2;m3=m2; v2=v1;m2=m1; v1=v0;m1=m0; v0=(a);m0=(m); } \
            else if ((a) > v1) { v3=v2;m3=m2; v2=v1;m2=m1; v1=(a);m1=(m); } \
            else if ((a) > v2) { v3=v2;m3=m2; v2=(a);m2=(m); } \
            else               { v3=(a);m3=(m); } \
        } } while (0)

    for (int m = lane; m < NN; m += 32) {
        float raw = sw[m];
        float a = (raw < -1e30f) ? -1.f : fmaxf(raw, 0.f) * invT;
        INSERT_CAND(a, m);
    }

    int base = (h * NN + n0 + w) * KK;
    float M = 0.f, ssel = 0.f;
    for (int k = 0; k < KK; k++) {
        float best = v0; int bm = m0;
#pragma unroll
        for (int o = 16; o; o >>= 1) {
            float ov = __shfl_xor_sync(0xffffffffu, best, o);
            int   oi = __shfl_xor_sync(0xffffffffu, bm,   o);
            if (ov > best || (ov == best && oi < bm)) { best = ov; bm = oi; }
        }
        if (k == 0) M = best;               // first pick is the row max
        float e = __expf(best - M);
        ssel += e;                           // identical on all lanes
        if (lane == 0) { g_tki[base + k] = bm; g_tkv[base + k] = e; }
        if (lane == (bm & 31)) {             // owner: mark + pop head
            sw[bm] = MARKV;
            v0 = v1; m0 = m1; v1 = v2; m1 = m2; v2 = v3; m2 = m3; v3 = -1.f;
            if (v0 < 0.f && k < KK - 1) {    // exhausted: rescan own strip (rare)
                v0 = v1 = v2 = v3 = -1.f;
                for (int m = lane; m < NN; m += 32) {
                    float raw = sw[m];
                    float a = (raw < -1e30f) ? -1.f : fmaxf(raw, 0.f) * invT;
                    INSERT_CAND(a, m);
                }
            }
        }
    }
#undef INSERT_CAND
    if (lane < KK) g_tkv[base + lane] = g_tkv[base + lane] / ssel;
}

// ---------------- 2: per-row union + edge MLP -> sparse rows + dense fa ----------------
// one warp per row i; grid = N/8 blocks of 256 threads
__global__ __launch_bounds__(256) void build_rows_kernel(
    const float* __restrict__ ew1, const float* __restrict__ eb1,
    const float* __restrict__ ew2, const float* __restrict__ eb2,
    float* __restrict__ fa)
{
    __shared__ float s_ew1[HH * 8];
    __shared__ float s_eb1[8];
    __shared__ float s_ew2[8];
    __shared__ int   s_js[8][80];
    __shared__ float s_vs[8][80];

    int tid = threadIdx.x;
    if (tid < 32) s_ew1[tid] = ew1[tid];
    else if (tid < 40) s_eb1[tid - 32] = eb1[tid - 32];
    else if (tid < 48) s_ew2[tid - 40] = ew2[tid - 40];
    float beta2 = eb2[0];
    __syncthreads();

    int w = tid >> 5, lane = tid & 31;
    int i = blockIdx.x * 8 + w;

    for (int e = lane; e < 80; e += 32) {
        int hh = e / KK, k = e % KK;
        s_js[w][e] = g_tki[(hh * NN + i) * KK + k];
        s_vs[w][e] = g_tkv[(hh * NN + i) * KK + k];
    }
    __syncwarp();

    int cnt = 0;
    for (int p = 0; p < 3; p++) {
        int e = lane + p * 32;
        bool owned = false;
        int j = -1;
        if (e < 80) {
            j = s_js[w][e];
            owned = true;
            for (int q = 0; q < e; q++)
                if (s_js[w][q] == j) { owned = false; break; }
        }
        unsigned bal = __ballot_sync(0xffffffffu, owned);
        int pos = cnt + __popc(bal & ((1u << lane) - 1u));
        if (owned) {
            float v[HH];
            float vsum = 0.f;
#pragma unroll
            for (int hh = 0; hh < HH; hh++) {
                float vv = 0.f;
                for (int k = 0; k < KK; k++)
                    if (s_js[w][hh * KK + k] == j) { vv = s_vs[w][hh * KK + k]; break; }
                v[hh] = vv; vsum += vv;
            }
            float ewv = beta2;
#pragma unroll
            for (int c = 0; c < 8; c++) {
                float hid = s_eb1[c];
#pragma unroll
                for (int hh = 0; hh < HH; hh++) hid = fmaf(v[hh], s_ew1[hh * 8 + c], hid);
                hid = fmaxf(hid, 0.f);
                ewv = fmaf(hid, s_ew2[c], ewv);
            }
            float sig  = 1.f / (1.f + __expf(-ewv));
            float favv = sig * (vsum * 0.25f);
            g_rowj[i * 80 + pos] = j;
            g_rowv[i * 80 + pos] = favv;
            atomicAdd(&g_colcnt[j], 1);
            fa[(size_t)i * NN + j] = favv;
        }
        cnt += __popc(bal);
    }
    if (lane == 0) g_rowcnt[i] = cnt;
}

// ---------------- 3: exclusive scan over column counts (single block) ----------------
__global__ __launch_bounds__(1024) void scan_kernel() {
    __shared__ int buf[1024];
    int t = threadIdx.x;
    int c0 = (2 * t     < NN) ? g_colcnt[2 * t]     : 0;
    int c1 = (2 * t + 1 < NN) ? g_colcnt[2 * t + 1] : 0;
    int psum = c0 + c1;
    buf[t] = psum;
    __syncthreads();
    for (int off = 1; off < 1024; off <<= 1) {
        int tmp = (t >= off) ? buf[t - off] : 0;
        __syncthreads();
        buf[t] += tmp;
        __syncthreads();
    }
    int base = buf[t] - psum;   // exclusive
    if (2 * t < NN)     { g_colptr[2 * t]     = base;      g_colcur[2 * t]     = base; }
    if (2 * t + 1 < NN) { g_colptr[2 * t + 1] = base + c0; g_colcur[2 * t + 1] = base + c0; }
}

// ---------------- 4: fill transposed (per-column) entry lists ----------------
__global__ void fill_kernel() {
    int i = blockIdx.x;
    int t = threadIdx.x;
    int cnt = g_rowcnt[i];
    if (t < cnt) {
        int j = g_rowj[i * 80 + t];
        int pos = atomicAdd(&g_colcur[j], 1);
        g_ci[pos] = i;
        g_cv[pos] = g_rowv[i * 80 + t];
    }
}

// ---------------- 5: support = fp16( xr @ W ), register-blocked 64x64 tile ----------------
#define XS_STRIDE 68
__global__ __launch_bounds__(128) void support_kernel(
    const float* __restrict__ x, const float* __restrict__ W)
{
    __shared__ float xs[64 * XS_STRIDE];
    __shared__ float wt[64 * XS_STRIDE];
    int tid = threadIdx.x;

    for (int k = tid; k < 1024; k += 128) {
        int d = k >> 4, o4 = (k & 15) * 4;
        float4 w = ((const float4*)W)[k];
        wt[(o4 + 0) * XS_STRIDE + d] = w.x;
        wt[(o4 + 1) * XS_STRIDE + d] = w.y;
        wt[(o4 + 2) * XS_STRIDE + d] = w.z;
        wt[(o4 + 3) * XS_STRIDE + d] = w.w;
    }
    int row0 = blockIdx.x * 64;
    for (int k = tid; k < 1024; k += 128) {
        int rr = k >> 4, f4 = k & 15;
        int r = row0 + rr;
        int bl = r / NN, n = r - bl * NN;
        int b = bl >> 5, l = bl & 31;
        float4 v = ((const float4*)(x + (((size_t)(b * NN + n) * 32) + l) * 64))[f4];
        *(float4*)&xs[rr * XS_STRIDE + f4 * 4] = v;
    }
    __syncthreads();

    int tr = tid & 7, to = tid >> 3;
    float acc[8][4];
#pragma unroll
    for (int i = 0; i < 8; i++)
#pragma unroll
        for (int j = 0; j < 4; j++) acc[i][j] = 0.f;

#pragma unroll 4
    for (int d4 = 0; d4 < 64; d4 += 4) {
        float4 xv[8], wv[4];
#pragma unroll
        for (int i = 0; i < 8; i++) xv[i] = *(const float4*)&xs[(tr + 8 * i) * XS_STRIDE + d4];
#pragma unroll
        for (int j = 0; j < 4; j++) wv[j] = *(const float4*)&wt[(to * 4 + j) * XS_STRIDE + d4];
#pragma unroll
        for (int i = 0; i < 8; i++)
#pragma unroll
            for (int j = 0; j < 4; j++) {
                acc[i][j] = fmaf(xv[i].x, wv[j].x, acc[i][j]);
                acc[i][j] = fmaf(xv[i].y, wv[j].y, acc[i][j]);
                acc[i][j] = fmaf(xv[i].z, wv[j].z, acc[i][j]);
                acc[i][j] = fmaf(xv[i].w, wv[j].w, acc[i][j]);
            }
    }

#pragma unroll
    for (int i = 0; i < 8; i++) {
        int r = row0 + tr + 8 * i;
        __half2 h0 = __floats2half2_rn(acc[i][0], acc[i][1]);
        __half2 h1 = __floats2half2_rn(acc[i][2], acc[i][3]);
        uint2 pk;
        pk.x = *(uint32_t*)&h0;
        pk.y = *(uint32_t*)&h1;
        *(uint2*)(g_supph + (size_t)r * 64 + to * 4) = pk;
    }
}

// ---------------- 6: sparse out[b,c,l,:] = sum_e w_e * support[bl, j_e, :] + bias ----------------
// one block per column c; 256 threads = 8 d-octets x 32 bl-groups; 4 bl iters
__global__ __launch_bounds__(256) void spmm_kernel(
    const float* __restrict__ bias, float* __restrict__ out)
{
    __shared__ int   sj[512];
    __shared__ float sv[512];
    int c = blockIdx.x;
    int tid = threadIdx.x;
    int q = tid & 7;        // d octet: d = 8q .. 8q+7
    int g = tid >> 3;       // 0..31
    int start = g_colptr[c], cnt = g_colcnt[c];

    float acc[4][8];
#pragma unroll
    for (int it = 0; it < 4; it++)
#pragma unroll
        for (int j = 0; j < 8; j++) acc[it][j] = 0.f;

    const uint4* supp4 = (const uint4*)g_supph;   // 8 halves per uint4

    for (int off = 0; off < cnt; off += 512) {
        int chunk = min(512, cnt - off);
        for (int e = tid; e < chunk; e += 256) {
            sj[e] = g_ci[start + off + e];
            sv[e] = g_cv[start + off + e];
        }
        __syncthreads();
        for (int e = 0; e < chunk; e++) {
            float wv = sv[e];
            int   i  = sj[e];
#pragma unroll
            for (int it = 0; it < 4; it++) {
                int bl = it * 32 + g;
                uint4 h4 = supp4[(size_t)(bl * NN + i) * 8 + q];
                const __half2* hh = (const __half2*)&h4;
#pragma unroll
                for (int j = 0; j < 4; j++) {
                    float2 f = __half22float2(hh[j]);
                    acc[it][2 * j]     = fmaf(wv, f.x, acc[it][2 * j]);
                    acc[it][2 * j + 1] = fmaf(wv, f.y, acc[it][2 * j + 1]);
                }
            }
        }
        __syncthreads();
    }

    float bv[8];
#pragma unroll
    for (int j = 0; j < 8; j++) bv[j] = bias[q * 8 + j];

#pragma unroll
    for (int it = 0; it < 4; it++) {
        int bl = it * 32 + g;
        int b = bl >> 5, l = bl & 31;
        float4 r0, r1;
        r0.x = acc[it][0] + bv[0]; r0.y = acc[it][1] + bv[1];
        r0.z = acc[it][2] + bv[2]; r0.w = acc[it][3] + bv[3];
        r1.x = acc[it][4] + bv[4]; r1.y = acc[it][5] + bv[5];
        r1.z = acc[it][6] + bv[6]; r1.w = acc[it][7] + bv[7];
        size_t ob = (size_t)((b * NN + c) * 32 + l) * 16 + q * 2;
        ((float4*)out)[ob]     = r0;
        ((float4*)out)[ob + 1] = r1;
    }
}

// ---------------- launch ----------------
extern "C" void kernel_launch(void* const* d_in, const int* in_sizes, int n_in,
                              void* d_out, int out_size)
{
    const float* x      = (const float*)d_in[0];
    const float* e1     = (const float*)d_in[1];
    const float* e2     = (const float*)d_in[2];
    const float* temp   = (const float*)d_in[3];
    const float* ew1    = (const float*)d_in[4];
    const float* eb1    = (const float*)d_in[5];
    const float* ew2    = (const float*)d_in[6];
    const float* eb2    = (const float*)d_in[7];
    const float* weight = (const float*)d_in[8];
    const float* bias   = (const float*)d_in[9];
    float* out = (float*)d_out;

    // final_adj destination: appended after out if there is room, else fallback scratch
    float* fa;
    if (out_size >= OUT_ELEMS + NN * NN) {
        fa = out + OUT_ELEMS;
    } else {
        void* p = nullptr;
        cudaGetSymbolAddress(&p, g_fa_fb);
        fa = (float*)p;
    }

    const int smem_scores = (TILE * NN + TILE * NDm) * sizeof(float);  // ~66 KB
    cudaFuncSetAttribute(scores_topk_kernel,
                         cudaFuncAttributeMaxDynamicSharedMemorySize, smem_scores);

    zero_kernel<<<2048, 256>>>(fa);
    scores_topk_kernel<<<HH * (NN / TILE), 256, smem_scores>>>(e1, e2, temp);
    build_rows_kernel<<<NN / 8, 256>>>(ew1, eb1, ew2, eb2, fa);
    scan_kernel<<<1, 1024>>>();
    fill_kernel<<<NN, 96>>>();
    support_kernel<<<(BLT * NN) / 64, 128>>>(x, weight);
    spmm_kernel<<<NN, 256>>>(bias, out);
}

// round 11
// speedup vs baseline: 1.7206x; 1.1177x over previous
#include <cuda_runtime.h>
#include <cuda_fp16.h>
#include <cstdint>

#define NN   2000
#define HH   4
#define NDm  64
#define KK   20
#define TILE 8
#define BLT  128          // B*L = 4*32
#define DD   64
#define OUT_ELEMS (4*2000*32*64)
#define NNZ_CAP   (NN*80)
#define MARKV (-3.0e38f)
#define XS_STRIDE 68

// ---------------- scratch (device globals; no allocation) ----------------
__device__ __align__(16) __half g_supph[(size_t)BLT*NN*DD];   // 32.8 MB fp16 support
__device__ int   g_tki[HH*NN*KK];
__device__ float g_tkv[HH*NN*KK];
__device__ int   g_rowj[NN*80];
__device__ float g_rowv[NN*80];
__device__ int   g_rowcnt[NN];
__device__ int   g_colcnt[NN];
__device__ int   g_colptr[NN];
__device__ int   g_colcur[NN];
__device__ int   g_ci[NNZ_CAP];
__device__ float g_cv[NNZ_CAP];
__device__ float g_fa_fb[(size_t)NN*NN];         // fallback final_adj (16 MB)

// ---------------- 0: zero counters + final_adj region ----------------
__global__ void zero_kernel(float* fa) {
    int idx = blockIdx.x * blockDim.x + threadIdx.x;
    if (idx < NN) g_colcnt[idx] = 0;
    size_t stride = (size_t)gridDim.x * blockDim.x;
    for (size_t p = idx; p < (size_t)NN * NN; p += stride) fa[p] = 0.f;
}

// ---------------- 1: FUSED scores+topk / support kernel ----------------
// grid = 3000 blocks of 256 threads, 66048 B dyn smem.
//   bx % 3 == 0  -> scores/topk block, id = bx/3           (1000 blocks)
//   else         -> support block,    id = bx - bx/3 - 1   (2000 blocks)
// Interleaving mixes L2-bound scores blocks with FMA/LSU-bound support
// blocks within every wave (true intra-launch overlap, no streams needed).
__global__ __launch_bounds__(256) void fused_scores_support_kernel(
    const float* __restrict__ e1, const float* __restrict__ e2,
    const float* __restrict__ temp,
    const float* __restrict__ x, const float* __restrict__ W)
{
    extern __shared__ float sm[];
    int bx = blockIdx.x;
    int tid = threadIdx.x;

    if (bx % 3 == 0) {
        // ================= scores + top-20 (identical math to R9) =================
        int sidb = bx / 3;
        float* s   = sm;                // [TILE][NN] raw scores
        float* e1s = sm + TILE * NN;    // [TILE][NDm]

        int h  = sidb / (NN / TILE);
        int n0 = (sidb % (NN / TILE)) * TILE;

        for (int i = tid; i < TILE * NDm; i += blockDim.x)
            e1s[i] = e1[((size_t)h * NN + n0 + i / NDm) * NDm + (i % NDm)];
        __syncthreads();

        for (int m = tid; m < NN; m += blockDim.x) {
            float acc[TILE];
#pragma unroll
            for (int r = 0; r < TILE; r++) acc[r] = 0.f;
            const float* e2p = e2 + (size_t)h * NDm * NN + m;
#pragma unroll 8
            for (int d = 0; d < NDm; d++) {
                float b = e2p[(size_t)d * NN];
#pragma unroll
                for (int r = 0; r < TILE; r++) acc[r] = fmaf(e1s[r * NDm + d], b, acc[r]);
            }
#pragma unroll
            for (int r = 0; r < TILE; r++) s[r * NN + m] = acc[r];   // raw
        }
        __syncthreads();

        int w = tid >> 5, lane = tid & 31;
        float invT = 1.0f / temp[h];
        float* sw = s + w * NN;

        float v0 = -1.f, v1 = -1.f, v2 = -1.f, v3 = -1.f;
        int   m0 = 0,    m1 = 0,    m2 = 0,    m3 = 0;
#define INSERT_CAND(a, m) do { \
            if ((a) > v3) { \
                if ((a) > v0)      { v3=v2;m3=m2; v2=v1;m2=m1; v1=v0;m1=m0; v0=(a);m0=(m); } \
                else if ((a) > v1) { v3=v2;m3=m2; v2=v1;m2=m1; v1=(a);m1=(m); } \
                else if ((a) > v2) { v3=v2;m3=m2; v2=(a);m2=(m); } \
                else               { v3=(a);m3=(m); } \
            } } while (0)

        for (int m = lane; m < NN; m += 32) {
            float raw = sw[m];
            float a = (raw < -1e30f) ? -1.f : fmaxf(raw, 0.f) * invT;
            INSERT_CAND(a, m);
        }

        int base = (h * NN + n0 + w) * KK;
        float M = 0.f, ssel = 0.f;
        for (int k = 0; k < KK; k++) {
            float best = v0; int bm = m0;
#pragma unroll
            for (int o = 16; o; o >>= 1) {
                float ov = __shfl_xor_sync(0xffffffffu, best, o);
                int   oi = __shfl_xor_sync(0xffffffffu, bm,   o);
                if (ov > best || (ov == best && oi < bm)) { best = ov; bm = oi; }
            }
            if (k == 0) M = best;
            float e = __expf(best - M);
            ssel += e;
            if (lane == 0) { g_tki[base + k] = bm; g_tkv[base + k] = e; }
            if (lane == (bm & 31)) {
                sw[bm] = MARKV;
                v0 = v1; m0 = m1; v1 = v2; m1 = m2; v2 = v3; m2 = m3; v3 = -1.f;
                if (v0 < 0.f && k < KK - 1) {
                    v0 = v1 = v2 = v3 = -1.f;
                    for (int m = lane; m < NN; m += 32) {
                        float raw = sw[m];
                        float a = (raw < -1e30f) ? -1.f : fmaxf(raw, 0.f) * invT;
                        INSERT_CAND(a, m);
                    }
                }
            }
        }
#undef INSERT_CAND
        if (lane < KK) g_tkv[base + lane] = g_tkv[base + lane] / ssel;

    } else {
        // ================= support = fp16( xr @ W ), 128 rows/block =================
        int sid = bx - bx / 3 - 1;       // 0..1999
        int row0 = sid * 128;
        float* xs = sm;                  // [128][XS_STRIDE]
        float* wt = sm + 128 * XS_STRIDE; // [64][XS_STRIDE]

        for (int k = tid; k < 1024; k += 256) {
            int d = k >> 4, o4 = (k & 15) * 4;
            float4 w = ((const float4*)W)[k];
            wt[(o4 + 0) * XS_STRIDE + d] = w.x;
            wt[(o4 + 1) * XS_STRIDE + d] = w.y;
            wt[(o4 + 2) * XS_STRIDE + d] = w.z;
            wt[(o4 + 3) * XS_STRIDE + d] = w.w;
        }
        for (int k = tid; k < 2048; k += 256) {
            int rr = k >> 4, f4 = k & 15;
            int r = row0 + rr;
            int bl = r / NN, n = r - bl * NN;
            int b = bl >> 5, l = bl & 31;
            float4 v = ((const float4*)(x + (((size_t)(b * NN + n) * 32) + l) * 64))[f4];
            *(float4*)&xs[rr * XS_STRIDE + f4 * 4] = v;
        }
        __syncthreads();

        int tr = tid & 15, to = tid >> 4;   // 16 row-groups x 16 col-groups
        float acc[8][4];
#pragma unroll
        for (int i = 0; i < 8; i++)
#pragma unroll
            for (int j = 0; j < 4; j++) acc[i][j] = 0.f;

#pragma unroll 4
        for (int d4 = 0; d4 < 64; d4 += 4) {
            float4 xv[8], wv[4];
#pragma unroll
            for (int i = 0; i < 8; i++) xv[i] = *(const float4*)&xs[(tr + 16 * i) * XS_STRIDE + d4];
#pragma unroll
            for (int j = 0; j < 4; j++) wv[j] = *(const float4*)&wt[(to * 4 + j) * XS_STRIDE + d4];
#pragma unroll
            for (int i = 0; i < 8; i++)
#pragma unroll
                for (int j = 0; j < 4; j++) {
                    acc[i][j] = fmaf(xv[i].x, wv[j].x, acc[i][j]);
                    acc[i][j] = fmaf(xv[i].y, wv[j].y, acc[i][j]);
                    acc[i][j] = fmaf(xv[i].z, wv[j].z, acc[i][j]);
                    acc[i][j] = fmaf(xv[i].w, wv[j].w, acc[i][j]);
                }
        }

#pragma unroll
        for (int i = 0; i < 8; i++) {
            int r = row0 + tr + 16 * i;
            __half2 h0 = __floats2half2_rn(acc[i][0], acc[i][1]);
            __half2 h1 = __floats2half2_rn(acc[i][2], acc[i][3]);
            uint2 pk;
            pk.x = *(uint32_t*)&h0;
            pk.y = *(uint32_t*)&h1;
            *(uint2*)(g_supph + (size_t)r * 64 + to * 4) = pk;
        }
    }
}

// ---------------- 2: per-row union + edge MLP -> sparse rows + dense fa ----------------
// one warp per row i; grid = N/8 blocks of 256 threads
__global__ __launch_bounds__(256) void build_rows_kernel(
    const float* __restrict__ ew1, const float* __restrict__ eb1,
    const float* __restrict__ ew2, const float* __restrict__ eb2,
    float* __restrict__ fa)
{
    __shared__ float s_ew1[HH * 8];
    __shared__ float s_eb1[8];
    __shared__ float s_ew2[8];
    __shared__ int   s_js[8][80];
    __shared__ float s_vs[8][80];

    int tid = threadIdx.x;
    if (tid < 32) s_ew1[tid] = ew1[tid];
    else if (tid < 40) s_eb1[tid - 32] = eb1[tid - 32];
    else if (tid < 48) s_ew2[tid - 40] = ew2[tid - 40];
    float beta2 = eb2[0];
    __syncthreads();

    int w = tid >> 5, lane = tid & 31;
    int i = blockIdx.x * 8 + w;

    for (int e = lane; e < 80; e += 32) {
        int hh = e / KK, k = e % KK;
        s_js[w][e] = g_tki[(hh * NN + i) * KK + k];
        s_vs[w][e] = g_tkv[(hh * NN + i) * KK + k];
    }
    __syncwarp();

    int cnt = 0;
    for (int p = 0; p < 3; p++) {
        int e = lane + p * 32;
        bool owned = false;
        int j = -1;
        if (e < 80) {
            j = s_js[w][e];
            owned = true;
            for (int q = 0; q < e; q++)
                if (s_js[w][q] == j) { owned = false; break; }
        }
        unsigned bal = __ballot_sync(0xffffffffu, owned);
        int pos = cnt + __popc(bal & ((1u << lane) - 1u));
        if (owned) {
            float v[HH];
            float vsum = 0.f;
#pragma unroll
            for (int hh = 0; hh < HH; hh++) {
                float vv = 0.f;
                for (int k = 0; k < KK; k++)
                    if (s_js[w][hh * KK + k] == j) { vv = s_vs[w][hh * KK + k]; break; }
                v[hh] = vv; vsum += vv;
            }
            float ewv = beta2;
#pragma unroll
            for (int c = 0; c < 8; c++) {
                float hid = s_eb1[c];
#pragma unroll
                for (int hh = 0; hh < HH; hh++) hid = fmaf(v[hh], s_ew1[hh * 8 + c], hid);
                hid = fmaxf(hid, 0.f);
                ewv = fmaf(hid, s_ew2[c], ewv);
            }
            float sig  = 1.f / (1.f + __expf(-ewv));
            float favv = sig * (vsum * 0.25f);
            g_rowj[i * 80 + pos] = j;
            g_rowv[i * 80 + pos] = favv;
            atomicAdd(&g_colcnt[j], 1);
            fa[(size_t)i * NN + j] = favv;
        }
        cnt += __popc(bal);
    }
    if (lane == 0) g_rowcnt[i] = cnt;
}

// ---------------- 3: exclusive scan over column counts (single block) ----------------
__global__ __launch_bounds__(1024) void scan_kernel() {
    __shared__ int buf[1024];
    int t = threadIdx.x;
    int c0 = (2 * t     < NN) ? g_colcnt[2 * t]     : 0;
    int c1 = (2 * t + 1 < NN) ? g_colcnt[2 * t + 1] : 0;
    int psum = c0 + c1;
    buf[t] = psum;
    __syncthreads();
    for (int off = 1; off < 1024; off <<= 1) {
        int tmp = (t >= off) ? buf[t - off] : 0;
        __syncthreads();
        buf[t] += tmp;
        __syncthreads();
    }
    int base = buf[t] - psum;   // exclusive
    if (2 * t < NN)     { g_colptr[2 * t]     = base;      g_colcur[2 * t]     = base; }
    if (2 * t + 1 < NN) { g_colptr[2 * t + 1] = base + c0; g_colcur[2 * t + 1] = base + c0; }
}

// ---------------- 4: fill transposed (per-column) entry lists ----------------
__global__ void fill_kernel() {
    int i = blockIdx.x;
    int t = threadIdx.x;
    int cnt = g_rowcnt[i];
    if (t < cnt) {
        int j = g_rowj[i * 80 + t];
        int pos = atomicAdd(&g_colcur[j], 1);
        g_ci[pos] = i;
        g_cv[pos] = g_rowv[i * 80 + t];
    }
}

// ---------------- 5: sparse out[b,c,l,:] = sum_e w_e * support[bl, j_e, :] + bias ----------------
// one block per column c; 256 threads = 8 d-octets x 32 bl-groups; 4 bl iters
__global__ __launch_bounds__(256) void spmm_kernel(
    const float* __restrict__ bias, float* __restrict__ out)
{
    __shared__ int   sj[512];
    __shared__ float sv[512];
    int c = blockIdx.x;
    int tid = threadIdx.x;
    int q = tid & 7;        // d octet: d = 8q .. 8q+7
    int g = tid >> 3;       // 0..31
    int start = g_colptr[c], cnt = g_colcnt[c];

    float acc[4][8];
#pragma unroll
    for (int it = 0; it < 4; it++)
#pragma unroll
        for (int j = 0; j < 8; j++) acc[it][j] = 0.f;

    const uint4* supp4 = (const uint4*)g_supph;   // 8 halves per uint4

    for (int off = 0; off < cnt; off += 512) {
        int chunk = min(512, cnt - off);
        for (int e = tid; e < chunk; e += 256) {
            sj[e] = g_ci[start + off + e];
            sv[e] = g_cv[start + off + e];
        }
        __syncthreads();
        for (int e = 0; e < chunk; e++) {
            float wv = sv[e];
            int   i  = sj[e];
#pragma unroll
            for (int it = 0; it < 4; it++) {
                int bl = it * 32 + g;
                uint4 h4 = supp4[(size_t)(bl * NN + i) * 8 + q];
                const __half2* hh = (const __half2*)&h4;
#pragma unroll
                for (int j = 0; j < 4; j++) {
                    float2 f = __half22float2(hh[j]);
                    acc[it][2 * j]     = fmaf(wv, f.x, acc[it][2 * j]);
                    acc[it][2 * j + 1] = fmaf(wv, f.y, acc[it][2 * j + 1]);
                }
            }
        }
        __syncthreads();
    }

    float bv[8];
#pragma unroll
    for (int j = 0; j < 8; j++) bv[j] = bias[q * 8 + j];

#pragma unroll
    for (int it = 0; it < 4; it++) {
        int bl = it * 32 + g;
        int b = bl >> 5, l = bl & 31;
        float4 r0, r1;
        r0.x = acc[it][0] + bv[0]; r0.y = acc[it][1] + bv[1];
        r0.z = acc[it][2] + bv[2]; r0.w = acc[it][3] + bv[3];
        r1.x = acc[it][4] + bv[4]; r1.y = acc[it][5] + bv[5];
        r1.z = acc[it][6] + bv[6]; r1.w = acc[it][7] + bv[7];
        size_t ob = (size_t)((b * NN + c) * 32 + l) * 16 + q * 2;
        ((float4*)out)[ob]     = r0;
        ((float4*)out)[ob + 1] = r1;
    }
}

// ---------------- launch ----------------
extern "C" void kernel_launch(void* const* d_in, const int* in_sizes, int n_in,
                              void* d_out, int out_size)
{
    const float* x      = (const float*)d_in[0];
    const float* e1     = (const float*)d_in[1];
    const float* e2     = (const float*)d_in[2];
    const float* temp   = (const float*)d_in[3];
    const float* ew1    = (const float*)d_in[4];
    const float* eb1    = (const float*)d_in[5];
    const float* ew2    = (const float*)d_in[6];
    const float* eb2    = (const float*)d_in[7];
    const float* weight = (const float*)d_in[8];
    const float* bias   = (const float*)d_in[9];
    float* out = (float*)d_out;

    // final_adj destination: appended after out if there is room, else fallback scratch
    float* fa;
    if (out_size >= OUT_ELEMS + NN * NN) {
        fa = out + OUT_ELEMS;
    } else {
        void* p = nullptr;
        cudaGetSymbolAddress(&p, g_fa_fb);
        fa = (float*)p;
    }

    const int smem_fused = (TILE * NN + TILE * NDm) * sizeof(float);  // 66048 B
    cudaFuncSetAttribute(fused_scores_support_kernel,
                         cudaFuncAttributeMaxDynamicSharedMemorySize, smem_fused);

    zero_kernel<<<2048, 256>>>(fa);
    fused_scores_support_kernel<<<3000, 256, smem_fused>>>(e1, e2, temp, x, weight);
    build_rows_kernel<<<NN / 8, 256>>>(ew1, eb1, ew2, eb2, fa);
    scan_kernel<<<1, 1024>>>();
    fill_kernel<<<NN, 96>>>();
    spmm_kernel<<<NN, 256>>>(bias, out);
}

// round 12
// speedup vs baseline: 1.8941x; 1.1009x over previous
#include <cuda_runtime.h>
#include <cuda_fp16.h>
#include <cstdint>

#define NN   2000
#define HH   4
#define NDm  64
#define KK   20
#define TILE 8
#define BLT  128          // B*L = 4*32
#define DD   64
#define OUT_ELEMS (4*2000*32*64)
#define NNZ_CAP   (NN*80)
#define MARKV (-3.0e38f)
#define XS_STRIDE 68

// ---------------- scratch (device globals; no allocation) ----------------
__device__ __align__(16) __half g_supph[(size_t)BLT*NN*DD];   // 32.8 MB fp16 support
__device__ int   g_tki[HH*NN*KK];
__device__ float g_tkv[HH*NN*KK];
__device__ int   g_rowj[NN*80];
__device__ float g_rowv[NN*80];
__device__ int   g_rowcnt[NN];
__device__ int   g_colcnt[NN];
__device__ int   g_colptr[NN];
__device__ int   g_colcur[NN];
__device__ int   g_ci[NNZ_CAP];
__device__ float g_cv[NNZ_CAP];
__device__ float g_fa_fb[(size_t)NN*NN];         // fallback final_adj (16 MB)

// ---------------- 0: zero counters + final_adj region ----------------
__global__ void zero_kernel(float* fa) {
    int idx = blockIdx.x * blockDim.x + threadIdx.x;
    if (idx < NN) g_colcnt[idx] = 0;
    size_t stride = (size_t)gridDim.x * blockDim.x;
    for (size_t p = idx; p < (size_t)NN * NN; p += stride) fa[p] = 0.f;
}

// ---------------- 1: FUSED scores+topk / support kernel ----------------
// grid = 3000 blocks of 256 threads, 66048 B dyn smem.
//   bx % 3 == 0  -> scores/topk block, id = bx/3           (1000 blocks)
//   else         -> support block,    id = bx - bx/3 - 1   (2000 blocks)
__global__ __launch_bounds__(256) void fused_scores_support_kernel(
    const float* __restrict__ e1, const float* __restrict__ e2,
    const float* __restrict__ temp,
    const float* __restrict__ x, const float* __restrict__ W)
{
    extern __shared__ float sm[];
    int bx = blockIdx.x;
    int tid = threadIdx.x;

    if (bx % 3 == 0) {
        // ================= scores + top-20 =================
        int sidb = bx / 3;
        float* s   = sm;                // [TILE][NN] raw scores
        float* e1s = sm + TILE * NN;    // [TILE][NDm]

        int h  = sidb / (NN / TILE);
        int n0 = (sidb % (NN / TILE)) * TILE;

        for (int i = tid; i < TILE * NDm; i += blockDim.x)
            e1s[i] = e1[((size_t)h * NN + n0 + i / NDm) * NDm + (i % NDm)];
        __syncthreads();

        // register-blocked GEMM: each thread -> all 8 rows x 4 consecutive m.
        // d ascends exactly as before => bitwise-identical accumulation.
        const float* e2h = e2 + (size_t)h * NDm * NN;
        for (int m0 = tid * 4; m0 < NN; m0 += 1024) {
            float acc[TILE][4];
#pragma unroll
            for (int r = 0; r < TILE; r++)
#pragma unroll
                for (int mm = 0; mm < 4; mm++) acc[r][mm] = 0.f;

#pragma unroll 4
            for (int d4 = 0; d4 < NDm; d4 += 4) {
                float4 e1v[TILE];
#pragma unroll
                for (int r = 0; r < TILE; r++)
                    e1v[r] = *(const float4*)&e1s[r * NDm + d4];
                float4 b0 = *(const float4*)(e2h + (size_t)(d4 + 0) * NN + m0);
                float4 b1 = *(const float4*)(e2h + (size_t)(d4 + 1) * NN + m0);
                float4 b2 = *(const float4*)(e2h + (size_t)(d4 + 2) * NN + m0);
                float4 b3 = *(const float4*)(e2h + (size_t)(d4 + 3) * NN + m0);
#pragma unroll
                for (int r = 0; r < TILE; r++) {
                    acc[r][0] = fmaf(e1v[r].x, b0.x, acc[r][0]);
                    acc[r][1] = fmaf(e1v[r].x, b0.y, acc[r][1]);
                    acc[r][2] = fmaf(e1v[r].x, b0.z, acc[r][2]);
                    acc[r][3] = fmaf(e1v[r].x, b0.w, acc[r][3]);
                    acc[r][0] = fmaf(e1v[r].y, b1.x, acc[r][0]);
                    acc[r][1] = fmaf(e1v[r].y, b1.y, acc[r][1]);
                    acc[r][2] = fmaf(e1v[r].y, b1.z, acc[r][2]);
                    acc[r][3] = fmaf(e1v[r].y, b1.w, acc[r][3]);
                    acc[r][0] = fmaf(e1v[r].z, b2.x, acc[r][0]);
                    acc[r][1] = fmaf(e1v[r].z, b2.y, acc[r][1]);
                    acc[r][2] = fmaf(e1v[r].z, b2.z, acc[r][2]);
                    acc[r][3] = fmaf(e1v[r].z, b2.w, acc[r][3]);
                    acc[r][0] = fmaf(e1v[r].w, b3.x, acc[r][0]);
                    acc[r][1] = fmaf(e1v[r].w, b3.y, acc[r][1]);
                    acc[r][2] = fmaf(e1v[r].w, b3.z, acc[r][2]);
                    acc[r][3] = fmaf(e1v[r].w, b3.w, acc[r][3]);
                }
            }
#pragma unroll
            for (int r = 0; r < TILE; r++)
                *(float4*)&s[r * NN + m0] = *(float4*)acc[r];
        }
        __syncthreads();

        int w = tid >> 5, lane = tid & 31;
        float invT = 1.0f / temp[h];
        float* sw = s + w * NN;

        float v0 = -1.f, v1 = -1.f, v2 = -1.f, v3 = -1.f;
        int   m0i = 0,   m1i = 0,   m2i = 0,   m3i = 0;
#define INSERT_CAND(a, m) do { \
            if ((a) > v3) { \
                if ((a) > v0)      { v3=v2;m3i=m2i; v2=v1;m2i=m1i; v1=v0;m1i=m0i; v0=(a);m0i=(m); } \
                else if ((a) > v1) { v3=v2;m3i=m2i; v2=v1;m2i=m1i; v1=(a);m1i=(m); } \
                else if ((a) > v2) { v3=v2;m3i=m2i; v2=(a);m2i=(m); } \
                else               { v3=(a);m3i=(m); } \
            } } while (0)

        for (int m = lane; m < NN; m += 32) {
            float raw = sw[m];
            float a = (raw < -1e30f) ? -1.f : fmaxf(raw, 0.f) * invT;
            INSERT_CAND(a, m);
        }

        int base = (h * NN + n0 + w) * KK;
        float M = 0.f, ssel = 0.f;
        for (int k = 0; k < KK; k++) {
            float best = v0; int bm = m0i;
#pragma unroll
            for (int o = 16; o; o >>= 1) {
                float ov = __shfl_xor_sync(0xffffffffu, best, o);
                int   oi = __shfl_xor_sync(0xffffffffu, bm,   o);
                if (ov > best || (ov == best && oi < bm)) { best = ov; bm = oi; }
            }
            if (k == 0) M = best;
            float e = __expf(best - M);
            ssel += e;
            if (lane == 0) { g_tki[base + k] = bm; g_tkv[base + k] = e; }
            if (lane == (bm & 31)) {
                sw[bm] = MARKV;
                v0 = v1; m0i = m1i; v1 = v2; m1i = m2i; v2 = v3; m2i = m3i; v3 = -1.f;
                if (v0 < 0.f && k < KK - 1) {
                    v0 = v1 = v2 = v3 = -1.f;
                    for (int m = lane; m < NN; m += 32) {
                        float raw = sw[m];
                        float a = (raw < -1e30f) ? -1.f : fmaxf(raw, 0.f) * invT;
                        INSERT_CAND(a, m);
                    }
                }
            }
        }
#undef INSERT_CAND
        if (lane < KK) g_tkv[base + lane] = g_tkv[base + lane] / ssel;

    } else {
        // ================= support = fp16( xr @ W ), 128 rows/block =================
        int sid = bx - bx / 3 - 1;       // 0..1999
        int row0 = sid * 128;
        float* xs = sm;                  // [128][XS_STRIDE]
        float* wt = sm + 128 * XS_STRIDE; // [64][XS_STRIDE]

        for (int k = tid; k < 1024; k += 256) {
            int d = k >> 4, o4 = (k & 15) * 4;
            float4 w = ((const float4*)W)[k];
            wt[(o4 + 0) * XS_STRIDE + d] = w.x;
            wt[(o4 + 1) * XS_STRIDE + d] = w.y;
            wt[(o4 + 2) * XS_STRIDE + d] = w.z;
            wt[(o4 + 3) * XS_STRIDE + d] = w.w;
        }
        for (int k = tid; k < 2048; k += 256) {
            int rr = k >> 4, f4 = k & 15;
            int r = row0 + rr;
            int bl = r / NN, n = r - bl * NN;
            int b = bl >> 5, l = bl & 31;
            float4 v = ((const float4*)(x + (((size_t)(b * NN + n) * 32) + l) * 64))[f4];
            *(float4*)&xs[rr * XS_STRIDE + f4 * 4] = v;
        }
        __syncthreads();

        int tr = tid & 15, to = tid >> 4;   // 16 row-groups x 16 col-groups
        float acc[8][4];
#pragma unroll
        for (int i = 0; i < 8; i++)
#pragma unroll
            for (int j = 0; j < 4; j++) acc[i][j] = 0.f;

#pragma unroll 4
        for (int d4 = 0; d4 < 64; d4 += 4) {
            float4 xv[8], wv[4];
#pragma unroll
            for (int i = 0; i < 8; i++) xv[i] = *(const float4*)&xs[(tr + 16 * i) * XS_STRIDE + d4];
#pragma unroll
            for (int j = 0; j < 4; j++) wv[j] = *(const float4*)&wt[(to * 4 + j) * XS_STRIDE + d4];
#pragma unroll
            for (int i = 0; i < 8; i++)
#pragma unroll
                for (int j = 0; j < 4; j++) {
                    acc[i][j] = fmaf(xv[i].x, wv[j].x, acc[i][j]);
                    acc[i][j] = fmaf(xv[i].y, wv[j].y, acc[i][j]);
                    acc[i][j] = fmaf(xv[i].z, wv[j].z, acc[i][j]);
                    acc[i][j] = fmaf(xv[i].w, wv[j].w, acc[i][j]);
                }
        }

#pragma unroll
        for (int i = 0; i < 8; i++) {
            int r = row0 + tr + 16 * i;
            __half2 h0 = __floats2half2_rn(acc[i][0], acc[i][1]);
            __half2 h1 = __floats2half2_rn(acc[i][2], acc[i][3]);
            uint2 pk;
            pk.x = *(uint32_t*)&h0;
            pk.y = *(uint32_t*)&h1;
            *(uint2*)(g_supph + (size_t)r * 64 + to * 4) = pk;
        }
    }
}

// ---------------- 2: per-row union + edge MLP -> sparse rows + dense fa ----------------
__global__ __launch_bounds__(256) void build_rows_kernel(
    const float* __restrict__ ew1, const float* __restrict__ eb1,
    const float* __restrict__ ew2, const float* __restrict__ eb2,
    float* __restrict__ fa)
{
    __shared__ float s_ew1[HH * 8];
    __shared__ float s_eb1[8];
    __shared__ float s_ew2[8];
    __shared__ int   s_js[8][80];
    __shared__ float s_vs[8][80];

    int tid = threadIdx.x;
    if (tid < 32) s_ew1[tid] = ew1[tid];
    else if (tid < 40) s_eb1[tid - 32] = eb1[tid - 32];
    else if (tid < 48) s_ew2[tid - 40] = ew2[tid - 40];
    float beta2 = eb2[0];
    __syncthreads();

    int w = tid >> 5, lane = tid & 31;
    int i = blockIdx.x * 8 + w;

    for (int e = lane; e < 80; e += 32) {
        int hh = e / KK, k = e % KK;
        s_js[w][e] = g_tki[(hh * NN + i) * KK + k];
        s_vs[w][e] = g_tkv[(hh * NN + i) * KK + k];
    }
    __syncwarp();

    int cnt = 0;
    for (int p = 0; p < 3; p++) {
        int e = lane + p * 32;
        bool owned = false;
        int j = -1;
        if (e < 80) {
            j = s_js[w][e];
            owned = true;
            for (int q = 0; q < e; q++)
                if (s_js[w][q] == j) { owned = false; break; }
        }
        unsigned bal = __ballot_sync(0xffffffffu, owned);
        int pos = cnt + __popc(bal & ((1u << lane) - 1u));
        if (owned) {
            float v[HH];
            float vsum = 0.f;
#pragma unroll
            for (int hh = 0; hh < HH; hh++) {
                float vv = 0.f;
                for (int k = 0; k < KK; k++)
                    if (s_js[w][hh * KK + k] == j) { vv = s_vs[w][hh * KK + k]; break; }
                v[hh] = vv; vsum += vv;
            }
            float ewv = beta2;
#pragma unroll
            for (int c = 0; c < 8; c++) {
                float hid = s_eb1[c];
#pragma unroll
                for (int hh = 0; hh < HH; hh++) hid = fmaf(v[hh], s_ew1[hh * 8 + c], hid);
                hid = fmaxf(hid, 0.f);
                ewv = fmaf(hid, s_ew2[c], ewv);
            }
            float sig  = 1.f / (1.f + __expf(-ewv));
            float favv = sig * (vsum * 0.25f);
            g_rowj[i * 80 + pos] = j;
            g_rowv[i * 80 + pos] = favv;
            atomicAdd(&g_colcnt[j], 1);
            fa[(size_t)i * NN + j] = favv;
        }
        cnt += __popc(bal);
    }
    if (lane == 0) g_rowcnt[i] = cnt;
}

// ---------------- 3: exclusive scan over column counts (single block) ----------------
__global__ __launch_bounds__(1024) void scan_kernel() {
    __shared__ int buf[1024];
    int t = threadIdx.x;
    int c0 = (2 * t     < NN) ? g_colcnt[2 * t]     : 0;
    int c1 = (2 * t + 1 < NN) ? g_colcnt[2 * t + 1] : 0;
    int psum = c0 + c1;
    buf[t] = psum;
    __syncthreads();
    for (int off = 1; off < 1024; off <<= 1) {
        int tmp = (t >= off) ? buf[t - off] : 0;
        __syncthreads();
        buf[t] += tmp;
        __syncthreads();
    }
    int base = buf[t] - psum;   // exclusive
    if (2 * t < NN)     { g_colptr[2 * t]     = base;      g_colcur[2 * t]     = base; }
    if (2 * t + 1 < NN) { g_colptr[2 * t + 1] = base + c0; g_colcur[2 * t + 1] = base + c0; }
}

// ---------------- 4: fill transposed (per-column) entry lists ----------------
__global__ void fill_kernel() {
    int i = blockIdx.x;
    int t = threadIdx.x;
    int cnt = g_rowcnt[i];
    if (t < cnt) {
        int j = g_rowj[i * 80 + t];
        int pos = atomicAdd(&g_colcur[j], 1);
        g_ci[pos] = i;
        g_cv[pos] = g_rowv[i * 80 + t];
    }
}

// ---------------- 5: sparse out[b,c,l,:] = sum_e w_e * support[bl, j_e, :] + bias ----------------
__global__ __launch_bounds__(256) void spmm_kernel(
    const float* __restrict__ bias, float* __restrict__ out)
{
    __shared__ int   sj[512];
    __shared__ float sv[512];
    int c = blockIdx.x;
    int tid = threadIdx.x;
    int q = tid & 7;        // d octet: d = 8q .. 8q+7
    int g = tid >> 3;       // 0..31
    int start = g_colptr[c], cnt = g_colcnt[c];

    float acc[4][8];
#pragma unroll
    for (int it = 0; it < 4; it++)
#pragma unroll
        for (int j = 0; j < 8; j++) acc[it][j] = 0.f;

    const uint4* supp4 = (const uint4*)g_supph;   // 8 halves per uint4

    for (int off = 0; off < cnt; off += 512) {
        int chunk = min(512, cnt - off);
        for (int e = tid; e < chunk; e += 256) {
            sj[e] = g_ci[start + off + e];
            sv[e] = g_cv[start + off + e];
        }
        __syncthreads();
        for (int e = 0; e < chunk; e++) {
            float wv = sv[e];
            int   i  = sj[e];
#pragma unroll
            for (int it = 0; it < 4; it++) {
                int bl = it * 32 + g;
                uint4 h4 = supp4[(size_t)(bl * NN + i) * 8 + q];
                const __half2* hh = (const __half2*)&h4;
#pragma unroll
                for (int j = 0; j < 4; j++) {
                    float2 f = __half22float2(hh[j]);
                    acc[it][2 * j]     = fmaf(wv, f.x, acc[it][2 * j]);
                    acc[it][2 * j + 1] = fmaf(wv, f.y, acc[it][2 * j + 1]);
                }
            }
        }
        __syncthreads();
    }

    float bv[8];
#pragma unroll
    for (int j = 0; j < 8; j++) bv[j] = bias[q * 8 + j];

#pragma unroll
    for (int it = 0; it < 4; it++) {
        int bl = it * 32 + g;
        int b = bl >> 5, l = bl & 31;
        float4 r0, r1;
        r0.x = acc[it][0] + bv[0]; r0.y = acc[it][1] + bv[1];
        r0.z = acc[it][2] + bv[2]; r0.w = acc[it][3] + bv[3];
        r1.x = acc[it][4] + bv[4]; r1.y = acc[it][5] + bv[5];
        r1.z = acc[it][6] + bv[6]; r1.w = acc[it][7] + bv[7];
        size_t ob = (size_t)((b * NN + c) * 32 + l) * 16 + q * 2;
        ((float4*)out)[ob]     = r0;
        ((float4*)out)[ob + 1] = r1;
    }
}

// ---------------- launch ----------------
extern "C" void kernel_launch(void* const* d_in, const int* in_sizes, int n_in,
                              void* d_out, int out_size)
{
    const float* x      = (const float*)d_in[0];
    const float* e1     = (const float*)d_in[1];
    const float* e2     = (const float*)d_in[2];
    const float* temp   = (const float*)d_in[3];
    const float* ew1    = (const float*)d_in[4];
    const float* eb1    = (const float*)d_in[5];
    const float* ew2    = (const float*)d_in[6];
    const float* eb2    = (const float*)d_in[7];
    const float* weight = (const float*)d_in[8];
    const float* bias   = (const float*)d_in[9];
    float* out = (float*)d_out;

    // final_adj destination: appended after out if there is room, else fallback scratch
    float* fa;
    if (out_size >= OUT_ELEMS + NN * NN) {
        fa = out + OUT_ELEMS;
    } else {
        void* p = nullptr;
        cudaGetSymbolAddress(&p, g_fa_fb);
        fa = (float*)p;
    }

    const int smem_fused = (TILE * NN + TILE * NDm) * sizeof(float);  // 66048 B
    cudaFuncSetAttribute(fused_scores_support_kernel,
                         cudaFuncAttributeMaxDynamicSharedMemorySize, smem_fused);

    zero_kernel<<<2048, 256>>>(fa);
    fused_scores_support_kernel<<<3000, 256, smem_fused>>>(e1, e2, temp, x, weight);
    build_rows_kernel<<<NN / 8, 256>>>(ew1, eb1, ew2, eb2, fa);
    scan_kernel<<<1, 1024>>>();
    fill_kernel<<<NN, 96>>>();
    spmm_kernel<<<NN, 256>>>(bias, out);
}